// round 1
// baseline (speedup 1.0000x reference)
#include <cuda_runtime.h>
#include <math.h>

// ---------------- problem constants ----------------
constexpr int BB   = 2;
constexpr int SEQ  = 2048;
constexpr int DMODEL = 2048;
constexpr int NH   = 16;     // query heads
constexpr int NKV  = 4;      // kv heads
constexpr int HD   = 128;    // head dim
constexpr int MROWS = BB * SEQ;           // 4096
constexpr int QE   = NH * HD;             // 2048
constexpr int KVE  = NKV * HD;            // 512

// ---------------- scratch (static device memory; no allocations) ------------
__device__ float g_q [(size_t)MROWS * QE];   // [B*S, H*DH]
__device__ float g_k [(size_t)MROWS * KVE];  // [B*S, KVH*DH]
__device__ float g_v [(size_t)MROWS * KVE];
__device__ float g_ao[(size_t)MROWS * QE];   // attention output

// ============================================================================
// SGEMM: C[M,N] = A[M,K] * B[N,K]^T   (both row-major, B stored [N,K])
// 128x128 block tile, BK=8, 8x8 per thread, 256 threads.
// ============================================================================
__global__ __launch_bounds__(256)
void sgemm_nt(const float* __restrict__ A,
              const float* __restrict__ Bw,
              float* __restrict__ C,
              int M, int N, int K)
{
    __shared__ float As[8][128];
    __shared__ float Bs[8][128];

    const int tid = threadIdx.x;
    const int tx  = tid & 15;
    const int ty  = tid >> 4;
    const int m0  = blockIdx.y * 128;
    const int n0  = blockIdx.x * 128;

    // load mapping: each thread loads one float4 of A and one of B per k-step
    const int lr = tid >> 1;        // row 0..127
    const int lk = (tid & 1) * 4;   // k offset 0 or 4

    const float* Aptr = A  + (size_t)(m0 + lr) * K + lk;
    const float* Bptr = Bw + (size_t)(n0 + lr) * K + lk;

    float acc[8][8];
    #pragma unroll
    for (int i = 0; i < 8; i++)
        #pragma unroll
        for (int j = 0; j < 8; j++) acc[i][j] = 0.f;

    for (int k0 = 0; k0 < K; k0 += 8) {
        float4 a4 = *(const float4*)(Aptr + k0);
        float4 b4 = *(const float4*)(Bptr + k0);
        __syncthreads();   // previous tile's compute must finish before overwrite
        As[lk + 0][lr] = a4.x; As[lk + 1][lr] = a4.y;
        As[lk + 2][lr] = a4.z; As[lk + 3][lr] = a4.w;
        Bs[lk + 0][lr] = b4.x; Bs[lk + 1][lr] = b4.y;
        Bs[lk + 2][lr] = b4.z; Bs[lk + 3][lr] = b4.w;
        __syncthreads();

        #pragma unroll
        for (int k = 0; k < 8; k++) {
            float af[8], bf[8];
            #pragma unroll
            for (int i = 0; i < 8; i++) af[i] = As[k][ty * 8 + i];
            #pragma unroll
            for (int j = 0; j < 8; j++) bf[j] = Bs[k][tx * 8 + j];
            #pragma unroll
            for (int i = 0; i < 8; i++)
                #pragma unroll
                for (int j = 0; j < 8; j++)
                    acc[i][j] = fmaf(af[i], bf[j], acc[i][j]);
        }
    }

    #pragma unroll
    for (int i = 0; i < 8; i++) {
        float* crow = C + (size_t)(m0 + ty * 8 + i) * N + n0 + tx * 8;
        *(float4*)(crow)     = make_float4(acc[i][0], acc[i][1], acc[i][2], acc[i][3]);
        *(float4*)(crow + 4) = make_float4(acc[i][4], acc[i][5], acc[i][6], acc[i][7]);
    }
}

// ============================================================================
// RoPE (interleaved pairs), in-place on [B*S, heads, HD]
// ============================================================================
__global__ __launch_bounds__(256)
void rope_kernel(float* __restrict__ t,
                 const float* __restrict__ cs,
                 const float* __restrict__ sn,
                 int heads, int total_pairs)
{
    int idx = blockIdx.x * blockDim.x + threadIdx.x;
    if (idx >= total_pairs) return;
    int p    = idx & 63;           // pair index within head (HD/2 = 64)
    int rest = idx >> 6;           // bs*heads + h
    int bs   = rest / heads;
    int s    = bs & (SEQ - 1);     // SEQ is power of two

    float c  = cs[s * 64 + p];
    float si = sn[s * 64 + p];
    float* base = t + (size_t)rest * HD + 2 * p;
    float e = base[0], o = base[1];
    base[0] = e * c - o * si;
    base[1] = e * si + o * c;
}

// ============================================================================
// Fused causal flash attention (fp32, online softmax)
// grid: (S/64, H, B), block 256. Br = Bc = 64, DH = 128.
// Smem: Qs 32KB + Ks 32KB + Vs 32KB + Ps ~17KB = 115712 B (dynamic).
// ============================================================================
__global__ __launch_bounds__(256)
void attn_kernel(const float* __restrict__ Qg,
                 const float* __restrict__ Kg,
                 const float* __restrict__ Vg,
                 float* __restrict__ Og)
{
    extern __shared__ float sm[];
    float* Qs = sm;                    // [64][128]
    float* Ks = sm + 64 * 128;         // [64][128]
    float* Vs = sm + 2 * 64 * 128;     // [64][128]
    float* Ps = sm + 3 * 64 * 128;     // [64][68]  (padded stride 68)

    const int qb = blockIdx.x;
    const int h  = blockIdx.y;
    const int b  = blockIdx.z;
    const int kh = h >> 2;             // N_REP = 4
    const int tid = threadIdx.x;
    const int tx = tid & 15;
    const int ty = tid >> 4;
    const int q0 = qb * 64;

    // load Q tile
    for (int i = tid; i < 64 * 32; i += 256) {
        int r  = i >> 5;
        int c4 = (i & 31) << 2;
        size_t gi = (((size_t)(b * SEQ + q0 + r) * NH + h) << 7) + c4;
        *(float4*)(Qs + r * 128 + c4) = *(const float4*)(Qg + gi);
    }

    float m_i[4], l_i[4];
    #pragma unroll
    for (int i = 0; i < 4; i++) { m_i[i] = -1e30f; l_i[i] = 0.f; }
    float o_acc[4][8];
    #pragma unroll
    for (int i = 0; i < 4; i++)
        #pragma unroll
        for (int c = 0; c < 8; c++) o_acc[i][c] = 0.f;

    const float scale = 0.08838834764831845f;   // 1/sqrt(128)

    for (int kb = 0; kb <= qb; kb++) {
        __syncthreads();   // Q-load done (iter 0) / previous PV done
        for (int i = tid; i < 64 * 32; i += 256) {
            int r  = i >> 5;
            int c4 = (i & 31) << 2;
            size_t gi = (((size_t)(b * SEQ + kb * 64 + r) * NKV + kh) << 7) + c4;
            *(float4*)(Ks + r * 128 + c4) = *(const float4*)(Kg + gi);
            *(float4*)(Vs + r * 128 + c4) = *(const float4*)(Vg + gi);
        }
        __syncthreads();

        // ---- S = Q K^T (4x4 per thread) ----
        float acc[4][4];
        #pragma unroll
        for (int i = 0; i < 4; i++)
            #pragma unroll
            for (int j = 0; j < 4; j++) acc[i][j] = 0.f;

        #pragma unroll 4
        for (int d = 0; d < 128; d++) {
            float qf[4], kf[4];
            #pragma unroll
            for (int i = 0; i < 4; i++) qf[i] = Qs[(4 * ty + i) * 128 + d];
            #pragma unroll
            for (int j = 0; j < 4; j++) kf[j] = Ks[(4 * tx + j) * 128 + d];
            #pragma unroll
            for (int i = 0; i < 4; i++)
                #pragma unroll
                for (int j = 0; j < 4; j++)
                    acc[i][j] = fmaf(qf[i], kf[j], acc[i][j]);
        }

        const bool diag = (kb == qb);

        // ---- scale, mask, online softmax ----
        #pragma unroll
        for (int i = 0; i < 4; i++) {
            const int qi = 4 * ty + i;
            #pragma unroll
            for (int j = 0; j < 4; j++) {
                float sc = acc[i][j] * scale;
                if (diag && (4 * tx + j) > qi) sc = -1e30f;
                acc[i][j] = sc;
            }
            float pm = fmaxf(fmaxf(acc[i][0], acc[i][1]),
                             fmaxf(acc[i][2], acc[i][3]));
            #pragma unroll
            for (int off = 8; off; off >>= 1)
                pm = fmaxf(pm, __shfl_xor_sync(0xffffffffu, pm, off, 16));

            float m_new = fmaxf(m_i[i], pm);
            float alpha = __expf(m_i[i] - m_new);
            m_i[i] = m_new;

            float rs = 0.f;
            #pragma unroll
            for (int j = 0; j < 4; j++) {
                float p = __expf(acc[i][j] - m_new);
                acc[i][j] = p;
                rs += p;
            }
            #pragma unroll
            for (int off = 8; off; off >>= 1)
                rs += __shfl_xor_sync(0xffffffffu, rs, off, 16);

            l_i[i] = l_i[i] * alpha + rs;
            #pragma unroll
            for (int c = 0; c < 8; c++) o_acc[i][c] *= alpha;
            #pragma unroll
            for (int j = 0; j < 4; j++)
                Ps[(4 * ty + i) * 68 + 4 * tx + j] = acc[i][j];
        }
        __syncthreads();

        // ---- O += P V (4 rows x 8 cols per thread) ----
        #pragma unroll 2
        for (int j = 0; j < 64; j++) {
            float pf[4];
            #pragma unroll
            for (int i = 0; i < 4; i++) pf[i] = Ps[(4 * ty + i) * 68 + j];
            float4 v0 = *(const float4*)(Vs + j * 128 + 8 * tx);
            float4 v1 = *(const float4*)(Vs + j * 128 + 8 * tx + 4);
            float vf[8] = {v0.x, v0.y, v0.z, v0.w, v1.x, v1.y, v1.z, v1.w};
            #pragma unroll
            for (int i = 0; i < 4; i++)
                #pragma unroll
                for (int c = 0; c < 8; c++)
                    o_acc[i][c] = fmaf(pf[i], vf[c], o_acc[i][c]);
        }
    }

    // ---- epilogue: normalize + write [B*S, H, DH] ----
    #pragma unroll
    for (int i = 0; i < 4; i++) {
        float inv = 1.f / l_i[i];
        size_t base = (((size_t)(b * SEQ + q0 + 4 * ty + i) * NH + h) << 7) + 8 * tx;
        *(float4*)(Og + base)     = make_float4(o_acc[i][0] * inv, o_acc[i][1] * inv,
                                                o_acc[i][2] * inv, o_acc[i][3] * inv);
        *(float4*)(Og + base + 4) = make_float4(o_acc[i][4] * inv, o_acc[i][5] * inv,
                                                o_acc[i][6] * inv, o_acc[i][7] * inv);
    }
}

// ============================================================================
// host launcher
// ============================================================================
extern "C" void kernel_launch(void* const* d_in, const int* in_sizes, int n_in,
                              void* d_out, int out_size)
{
    const float* x  = (const float*)d_in[0];
    const float* fc = (const float*)d_in[1];
    const float* fs = (const float*)d_in[2];
    // d_in[3] = mask: replicated analytically (strict causal), unused
    const float* wq = (const float*)d_in[4];
    const float* wk = (const float*)d_in[5];
    const float* wv = (const float*)d_in[6];
    const float* wo = (const float*)d_in[7];
    float* out = (float*)d_out;

    float *q, *k, *v, *ao;
    cudaGetSymbolAddress((void**)&q,  g_q);
    cudaGetSymbolAddress((void**)&k,  g_k);
    cudaGetSymbolAddress((void**)&v,  g_v);
    cudaGetSymbolAddress((void**)&ao, g_ao);

    // QKV projections
    sgemm_nt<<<dim3(QE  / 128, MROWS / 128), 256>>>(x, wq, q, MROWS, QE,  DMODEL);
    sgemm_nt<<<dim3(KVE / 128, MROWS / 128), 256>>>(x, wk, k, MROWS, KVE, DMODEL);
    sgemm_nt<<<dim3(KVE / 128, MROWS / 128), 256>>>(x, wv, v, MROWS, KVE, DMODEL);

    // RoPE on Q and K
    {
        int tp_q = MROWS * NH  * (HD / 2);
        int tp_k = MROWS * NKV * (HD / 2);
        rope_kernel<<<(tp_q + 255) / 256, 256>>>(q, fc, fs, NH,  tp_q);
        rope_kernel<<<(tp_k + 255) / 256, 256>>>(k, fc, fs, NKV, tp_k);
    }

    // fused causal attention
    {
        const int smem = (3 * 64 * 128 + 64 * 68) * (int)sizeof(float); // 115712
        cudaFuncSetAttribute(attn_kernel,
                             cudaFuncAttributeMaxDynamicSharedMemorySize, smem);
        attn_kernel<<<dim3(SEQ / 64, NH, BB), 256, smem>>>(q, k, v, ao);
    }

    // output projection
    sgemm_nt<<<dim3(DMODEL / 128, MROWS / 128), 256>>>(ao, wo, out, MROWS, DMODEL, DMODEL);
}

// round 3
// speedup vs baseline: 1.9602x; 1.9602x over previous
#include <cuda_runtime.h>
#include <cuda_bf16.h>
#include <math.h>
#include <cstdint>

// ---------------- problem constants ----------------
constexpr int BB     = 2;
constexpr int SEQ    = 2048;
constexpr int DMODEL = 2048;
constexpr int NH     = 16;
constexpr int NKV    = 4;
constexpr int HD     = 128;
constexpr int MROWS  = BB * SEQ;     // 4096
constexpr int QE     = NH * HD;      // 2048
constexpr int KVE    = NKV * HD;     // 512
constexpr int K3     = 3 * DMODEL;   // 6144 (split-bf16 tripled K)
constexpr int NCHUNK = K3 / 32;      // 192 chunks of BK=32

// ---------------- scratch (static device memory) ----------------
__device__ float g_q [(size_t)MROWS * QE];
__device__ float g_k [(size_t)MROWS * KVE];
__device__ float g_v [(size_t)MROWS * KVE];
__device__ float g_ao[(size_t)MROWS * QE];

__device__ __nv_bfloat16 g_xc [(size_t)MROWS  * K3];
__device__ __nv_bfloat16 g_aoc[(size_t)MROWS  * K3];
__device__ __nv_bfloat16 g_wqc[(size_t)QE     * K3];
__device__ __nv_bfloat16 g_wkc[(size_t)KVE    * K3];
__device__ __nv_bfloat16 g_wvc[(size_t)KVE    * K3];
__device__ __nv_bfloat16 g_woc[(size_t)DMODEL * K3];

// ---------------- helpers ----------------
__device__ __forceinline__ uint32_t smem_u32(const void* p) {
    uint32_t a;
    asm("{ .reg .u64 t; cvta.to.shared.u64 t, %1; cvt.u32.u64 %0, t; }"
        : "=r"(a) : "l"(p));
    return a;
}
__device__ __forceinline__ void cp16(uint32_t dst, const void* src) {
    asm volatile("cp.async.cg.shared.global [%0], [%1], 16;"
                 :: "r"(dst), "l"(src));
}
__device__ __forceinline__ void ldsm_x4(uint32_t* r, uint32_t addr) {
    asm volatile("ldmatrix.sync.aligned.m8n8.x4.shared.b16 {%0,%1,%2,%3}, [%4];"
                 : "=r"(r[0]), "=r"(r[1]), "=r"(r[2]), "=r"(r[3]) : "r"(addr));
}
__device__ __forceinline__ void mma_bf16(float* d, const uint32_t* a,
                                         const uint32_t* b) {
    asm volatile(
        "mma.sync.aligned.m16n8k16.row.col.f32.bf16.bf16.f32 "
        "{%0,%1,%2,%3}, {%4,%5,%6,%7}, {%8,%9}, {%0,%1,%2,%3};"
        : "+f"(d[0]), "+f"(d[1]), "+f"(d[2]), "+f"(d[3])
        : "r"(a[0]), "r"(a[1]), "r"(a[2]), "r"(a[3]), "r"(b[0]), "r"(b[1]));
}

// ============================================================================
// split-bf16 conversion: row K3 layout [hi | act?lo:hi | act?hi:lo]
// ============================================================================
__global__ __launch_bounds__(256)
void convert_split(const float4* __restrict__ src, __nv_bfloat16* __restrict__ dst,
                   size_t total4, int act)
{
    size_t i = (size_t)blockIdx.x * blockDim.x + threadIdx.x;
    if (i >= total4) return;
    float4 v = src[i];
    size_t e = i * 4;
    size_t r = e >> 11;            // K = 2048
    int    c = (int)(e & 2047);
    float xs[4] = {v.x, v.y, v.z, v.w};
    __nv_bfloat16* d = dst + r * (size_t)K3 + c;
    #pragma unroll
    for (int j = 0; j < 4; j++) {
        __nv_bfloat16 h = __float2bfloat16(xs[j]);
        __nv_bfloat16 l = __float2bfloat16(xs[j] - __bfloat162float(h));
        d[j]              = h;
        d[DMODEL + j]     = act ? l : h;
        d[2 * DMODEL + j] = act ? h : l;
    }
}

// ============================================================================
// bf16 mma.sync GEMM: C[M,N] = A[M,K3] * B[N,K3]^T, fp32 out
// 128x128 tile, BK=32, 8 warps (64x32 each), cp.async double buffer
// smem row stride 40 bf16 (80B) -> ldmatrix conflict-free
// ============================================================================
constexpr int GSTRIDE = 40;                       // bf16 per smem row
constexpr int GBUF    = 128 * GSTRIDE * 2;        // 10240 B per tile buffer
constexpr int GEMM_SMEM = 4 * GBUF;               // A0 A1 B0 B1

__global__ __launch_bounds__(256)
void bgemm(const __nv_bfloat16* __restrict__ A,
           const __nv_bfloat16* __restrict__ B,
           float* __restrict__ C, int N)
{
    extern __shared__ char sm[];
    const uint32_t sA = smem_u32(sm);            // A buffers at 0, 10240
    const uint32_t sB = sA + 2 * GBUF;           // B buffers at 20480, 30720

    const int tid = threadIdx.x;
    const int wid = tid >> 5;
    const int lane = tid & 31;
    const int m0 = blockIdx.y * 128;
    const int n0 = blockIdx.x * 128;
    const int wm = (wid >> 2) * 64;              // warp m offset (0/64)
    const int wn = (wid & 3) * 32;               // warp n offset

    const __nv_bfloat16* Abase = A + (size_t)m0 * K3;
    const __nv_bfloat16* Bbase = B + (size_t)n0 * K3;

    // ldmatrix lane addresses (buffer 0, k-section 0)
    const int grp = lane >> 3, lr = lane & 7;
    uint32_t aaddr[4], baddr[2];
    #pragma unroll
    for (int mf = 0; mf < 4; mf++) {
        int row = wm + mf * 16 + (grp & 1) * 8 + lr;
        aaddr[mf] = sA + row * (GSTRIDE * 2) + (grp >> 1) * 16;
    }
    #pragma unroll
    for (int nf2 = 0; nf2 < 2; nf2++) {
        int row = wn + nf2 * 16 + (grp >> 1) * 8 + lr;
        baddr[nf2] = sB + row * (GSTRIDE * 2) + (grp & 1) * 16;
    }

    float acc[4][4][4];
    #pragma unroll
    for (int mf = 0; mf < 4; mf++)
        #pragma unroll
        for (int nf = 0; nf < 4; nf++)
            #pragma unroll
            for (int e = 0; e < 4; e++) acc[mf][nf][e] = 0.f;

    // ---- issue loads for chunk c into buffer c&1 ----
    auto issue = [&](int c) {
        const int buf = c & 1;
        const __nv_bfloat16* Ag = Abase + c * 32;
        const __nv_bfloat16* Bg = Bbase + c * 32;
        #pragma unroll
        for (int t = 0; t < 2; t++) {
            int i = tid + t * 256;
            int row = i >> 2, seg = i & 3;
            cp16(sA + buf * GBUF + row * (GSTRIDE * 2) + seg * 16,
                 Ag + (size_t)row * K3 + seg * 8);
        }
        #pragma unroll
        for (int t = 0; t < 2; t++) {
            int i = tid + t * 256;
            int row = i >> 2, seg = i & 3;
            cp16(sB + buf * GBUF + row * (GSTRIDE * 2) + seg * 16,
                 Bg + (size_t)row * K3 + seg * 8);
        }
    };

    issue(0);
    asm volatile("cp.async.commit_group;" ::: "memory");

    for (int c = 0; c < NCHUNK; c++) {
        asm volatile("cp.async.wait_group 0;" ::: "memory");
        __syncthreads();
        if (c + 1 < NCHUNK) {
            issue(c + 1);
            asm volatile("cp.async.commit_group;" ::: "memory");
        }
        const uint32_t boff = (c & 1) * GBUF;

        #pragma unroll
        for (int s = 0; s < 2; s++) {
            const uint32_t koff = boff + s * 32;   // 16 bf16 = 32 B
            uint32_t ar[4][4], br[2][4];
            #pragma unroll
            for (int mf = 0; mf < 4; mf++) ldsm_x4(ar[mf], aaddr[mf] + koff);
            #pragma unroll
            for (int nf2 = 0; nf2 < 2; nf2++) ldsm_x4(br[nf2], baddr[nf2] + koff);
            #pragma unroll
            for (int mf = 0; mf < 4; mf++)
                #pragma unroll
                for (int nf = 0; nf < 4; nf++)
                    mma_bf16(acc[mf][nf], ar[mf], &br[nf >> 1][(nf & 1) * 2]);
        }
        __syncthreads();
    }

    // ---- epilogue: direct float2 stores ----
    const int lr4 = lane >> 2, lc2 = (lane & 3) * 2;
    #pragma unroll
    for (int mf = 0; mf < 4; mf++) {
        int r = m0 + wm + mf * 16 + lr4;
        #pragma unroll
        for (int nf = 0; nf < 4; nf++) {
            int cc = n0 + wn + nf * 8 + lc2;
            *(float2*)(C + (size_t)r * N + cc) =
                make_float2(acc[mf][nf][0], acc[mf][nf][1]);
            *(float2*)(C + (size_t)(r + 8) * N + cc) =
                make_float2(acc[mf][nf][2], acc[mf][nf][3]);
        }
    }
}

// ============================================================================
// RoPE
// ============================================================================
__global__ __launch_bounds__(256)
void rope_kernel(float* __restrict__ t,
                 const float* __restrict__ cs,
                 const float* __restrict__ sn,
                 int heads, int total_pairs)
{
    int idx = blockIdx.x * blockDim.x + threadIdx.x;
    if (idx >= total_pairs) return;
    int p    = idx & 63;
    int rest = idx >> 6;
    int bs   = rest / heads;
    int s    = bs & (SEQ - 1);

    float c  = cs[s * 64 + p];
    float si = sn[s * 64 + p];
    float* base = t + (size_t)rest * HD + 2 * p;
    float e = base[0], o = base[1];
    base[0] = e * c - o * si;
    base[1] = e * si + o * c;
}

// ============================================================================
// Fused causal flash attention (fp32) — K stored transposed in smem
// ============================================================================
__global__ __launch_bounds__(256)
void attn_kernel(const float* __restrict__ Qg,
                 const float* __restrict__ Kg,
                 const float* __restrict__ Vg,
                 float* __restrict__ Og)
{
    extern __shared__ float smf[];
    float* Qs = smf;                   // [64][128]
    float* Kt = smf + 64 * 128;        // [128][64]  (d-major, transposed)
    float* Vs = smf + 2 * 64 * 128;    // [64][128]
    float* Ps = smf + 3 * 64 * 128;    // [64][68]

    const int qb = gridDim.x - 1 - blockIdx.x;   // heavy blocks first
    const int h  = blockIdx.y;
    const int b  = blockIdx.z;
    const int kh = h >> 2;
    const int tid = threadIdx.x;
    const int tx = tid & 15;
    const int ty = tid >> 4;
    const int q0 = qb * 64;

    for (int i = tid; i < 64 * 32; i += 256) {
        int r  = i >> 5;
        int c4 = (i & 31) << 2;
        size_t gi = (((size_t)(b * SEQ + q0 + r) * NH + h) << 7) + c4;
        *(float4*)(Qs + r * 128 + c4) = *(const float4*)(Qg + gi);
    }

    float m_i[4], l_i[4];
    #pragma unroll
    for (int i = 0; i < 4; i++) { m_i[i] = -1e30f; l_i[i] = 0.f; }
    float o_acc[4][8];
    #pragma unroll
    for (int i = 0; i < 4; i++)
        #pragma unroll
        for (int c = 0; c < 8; c++) o_acc[i][c] = 0.f;

    const float scale = 0.08838834764831845f;

    for (int kb = 0; kb <= qb; kb++) {
        __syncthreads();
        for (int i = tid; i < 64 * 32; i += 256) {
            int r  = i >> 5;
            int c4 = (i & 31) << 2;
            size_t gi = (((size_t)(b * SEQ + kb * 64 + r) * NKV + kh) << 7) + c4;
            float4 kv = *(const float4*)(Kg + gi);
            Kt[(c4 + 0) * 64 + r] = kv.x;
            Kt[(c4 + 1) * 64 + r] = kv.y;
            Kt[(c4 + 2) * 64 + r] = kv.z;
            Kt[(c4 + 3) * 64 + r] = kv.w;
            *(float4*)(Vs + r * 128 + c4) = *(const float4*)(Vg + gi);
        }
        __syncthreads();

        // ---- S = Q K^T : q broadcast (float2 over d), k conflict-free float4
        float acc[4][4];
        #pragma unroll
        for (int i = 0; i < 4; i++)
            #pragma unroll
            for (int j = 0; j < 4; j++) acc[i][j] = 0.f;

        #pragma unroll 4
        for (int d = 0; d < 128; d += 2) {
            float2 q2[4];
            #pragma unroll
            for (int i = 0; i < 4; i++)
                q2[i] = *(const float2*)(Qs + (4 * ty + i) * 128 + d);
            float4 ka = *(const float4*)(Kt + d * 64 + 4 * tx);
            float4 kb4 = *(const float4*)(Kt + (d + 1) * 64 + 4 * tx);
            float kaf[4] = {ka.x, ka.y, ka.z, ka.w};
            float kbf[4] = {kb4.x, kb4.y, kb4.z, kb4.w};
            #pragma unroll
            for (int i = 0; i < 4; i++)
                #pragma unroll
                for (int j = 0; j < 4; j++) {
                    acc[i][j] = fmaf(q2[i].x, kaf[j], acc[i][j]);
                    acc[i][j] = fmaf(q2[i].y, kbf[j], acc[i][j]);
                }
        }

        const bool diag = (kb == qb);

        #pragma unroll
        for (int i = 0; i < 4; i++) {
            const int qi = 4 * ty + i;
            #pragma unroll
            for (int j = 0; j < 4; j++) {
                float sc = acc[i][j] * scale;
                if (diag && (4 * tx + j) > qi) sc = -1e30f;
                acc[i][j] = sc;
            }
            float pm = fmaxf(fmaxf(acc[i][0], acc[i][1]),
                             fmaxf(acc[i][2], acc[i][3]));
            #pragma unroll
            for (int off = 8; off; off >>= 1)
                pm = fmaxf(pm, __shfl_xor_sync(0xffffffffu, pm, off, 16));

            float m_new = fmaxf(m_i[i], pm);
            float alpha = __expf(m_i[i] - m_new);
            m_i[i] = m_new;

            float rs = 0.f;
            #pragma unroll
            for (int j = 0; j < 4; j++) {
                float p = __expf(acc[i][j] - m_new);
                acc[i][j] = p;
                rs += p;
            }
            #pragma unroll
            for (int off = 8; off; off >>= 1)
                rs += __shfl_xor_sync(0xffffffffu, rs, off, 16);

            l_i[i] = l_i[i] * alpha + rs;
            #pragma unroll
            for (int c = 0; c < 8; c++) o_acc[i][c] *= alpha;
            #pragma unroll
            for (int j = 0; j < 4; j++)
                Ps[(4 * ty + i) * 68 + 4 * tx + j] = acc[i][j];
        }
        __syncthreads();

        #pragma unroll 2
        for (int j = 0; j < 64; j++) {
            float pf[4];
            #pragma unroll
            for (int i = 0; i < 4; i++) pf[i] = Ps[(4 * ty + i) * 68 + j];
            float4 v0 = *(const float4*)(Vs + j * 128 + 8 * tx);
            float4 v1 = *(const float4*)(Vs + j * 128 + 8 * tx + 4);
            float vf[8] = {v0.x, v0.y, v0.z, v0.w, v1.x, v1.y, v1.z, v1.w};
            #pragma unroll
            for (int i = 0; i < 4; i++)
                #pragma unroll
                for (int c = 0; c < 8; c++)
                    o_acc[i][c] = fmaf(pf[i], vf[c], o_acc[i][c]);
        }
    }

    #pragma unroll
    for (int i = 0; i < 4; i++) {
        float inv = 1.f / l_i[i];
        size_t base = (((size_t)(b * SEQ + q0 + 4 * ty + i) * NH + h) << 7) + 8 * tx;
        *(float4*)(Og + base)     = make_float4(o_acc[i][0] * inv, o_acc[i][1] * inv,
                                                o_acc[i][2] * inv, o_acc[i][3] * inv);
        *(float4*)(Og + base + 4) = make_float4(o_acc[i][4] * inv, o_acc[i][5] * inv,
                                                o_acc[i][6] * inv, o_acc[i][7] * inv);
    }
}

// ============================================================================
// host launcher
// ============================================================================
extern "C" void kernel_launch(void* const* d_in, const int* in_sizes, int n_in,
                              void* d_out, int out_size)
{
    const float* x  = (const float*)d_in[0];
    const float* fc = (const float*)d_in[1];
    const float* fs = (const float*)d_in[2];
    const float* wq = (const float*)d_in[4];
    const float* wk = (const float*)d_in[5];
    const float* wv = (const float*)d_in[6];
    const float* wo = (const float*)d_in[7];
    float* out = (float*)d_out;

    float *q, *k, *v, *ao;
    __nv_bfloat16 *xc, *aoc, *wqc, *wkc, *wvc, *woc;
    cudaGetSymbolAddress((void**)&q,   g_q);
    cudaGetSymbolAddress((void**)&k,   g_k);
    cudaGetSymbolAddress((void**)&v,   g_v);
    cudaGetSymbolAddress((void**)&ao,  g_ao);
    cudaGetSymbolAddress((void**)&xc,  g_xc);
    cudaGetSymbolAddress((void**)&aoc, g_aoc);
    cudaGetSymbolAddress((void**)&wqc, g_wqc);
    cudaGetSymbolAddress((void**)&wkc, g_wkc);
    cudaGetSymbolAddress((void**)&wvc, g_wvc);
    cudaGetSymbolAddress((void**)&woc, g_woc);

    cudaFuncSetAttribute(bgemm, cudaFuncAttributeMaxDynamicSharedMemorySize,
                         GEMM_SMEM);
    const int ATTN_SMEM = (3 * 64 * 128 + 64 * 68) * (int)sizeof(float);
    cudaFuncSetAttribute(attn_kernel, cudaFuncAttributeMaxDynamicSharedMemorySize,
                         ATTN_SMEM);

    // ---- split-bf16 conversions ----
    {
        size_t t4;
        t4 = (size_t)MROWS * DMODEL / 4;
        convert_split<<<(unsigned)((t4 + 255) / 256), 256>>>((const float4*)x,  xc,  t4, 1);
        t4 = (size_t)QE * DMODEL / 4;
        convert_split<<<(unsigned)((t4 + 255) / 256), 256>>>((const float4*)wq, wqc, t4, 0);
        t4 = (size_t)KVE * DMODEL / 4;
        convert_split<<<(unsigned)((t4 + 255) / 256), 256>>>((const float4*)wk, wkc, t4, 0);
        convert_split<<<(unsigned)((t4 + 255) / 256), 256>>>((const float4*)wv, wvc, t4, 0);
        t4 = (size_t)DMODEL * DMODEL / 4;
        convert_split<<<(unsigned)((t4 + 255) / 256), 256>>>((const float4*)wo, woc, t4, 0);
    }

    // ---- QKV projections (HMMA) ----
    bgemm<<<dim3(QE  / 128, MROWS / 128), 256, GEMM_SMEM>>>(xc, wqc, q, QE);
    bgemm<<<dim3(KVE / 128, MROWS / 128), 256, GEMM_SMEM>>>(xc, wkc, k, KVE);
    bgemm<<<dim3(KVE / 128, MROWS / 128), 256, GEMM_SMEM>>>(xc, wvc, v, KVE);

    // ---- RoPE ----
    {
        int tp_q = MROWS * NH  * (HD / 2);
        int tp_k = MROWS * NKV * (HD / 2);
        rope_kernel<<<(tp_q + 255) / 256, 256>>>(q, fc, fs, NH,  tp_q);
        rope_kernel<<<(tp_k + 255) / 256, 256>>>(k, fc, fs, NKV, tp_k);
    }

    // ---- fused causal attention (fp32) ----
    attn_kernel<<<dim3(SEQ / 64, NH, BB), 256, ATTN_SMEM>>>(q, k, v, ao);

    // ---- output projection ----
    {
        size_t t4 = (size_t)MROWS * DMODEL / 4;
        convert_split<<<(unsigned)((t4 + 255) / 256), 256>>>((const float4*)ao, aoc, t4, 1);
    }
    bgemm<<<dim3(DMODEL / 128, MROWS / 128), 256, GEMM_SMEM>>>(aoc, woc, out, MROWS == 0 ? DMODEL : DMODEL);
}

// round 4
// speedup vs baseline: 3.9324x; 2.0062x over previous
#include <cuda_runtime.h>
#include <cuda_bf16.h>
#include <math.h>
#include <cstdint>

// ---------------- problem constants ----------------
constexpr int BB     = 2;
constexpr int SEQ    = 2048;
constexpr int DMODEL = 2048;
constexpr int NH     = 16;
constexpr int NKV    = 4;
constexpr int HD     = 128;
constexpr int MROWS  = BB * SEQ;     // 4096
constexpr int QE     = NH * HD;      // 2048
constexpr int KVE    = NKV * HD;     // 512
constexpr int K3     = 3 * DMODEL;   // 6144
constexpr int NCHUNK = K3 / 32;      // 192

// ---------------- scratch ----------------
__device__ float g_q [(size_t)MROWS * QE];
__device__ float g_k [(size_t)MROWS * KVE];
__device__ float g_v [(size_t)MROWS * KVE];
__device__ float g_ao[(size_t)MROWS * QE];

__device__ __nv_bfloat16 g_xc [(size_t)MROWS  * K3];
__device__ __nv_bfloat16 g_aoc[(size_t)MROWS  * K3];
__device__ __nv_bfloat16 g_wqc[(size_t)QE     * K3];
__device__ __nv_bfloat16 g_wkc[(size_t)KVE    * K3];
__device__ __nv_bfloat16 g_wvc[(size_t)KVE    * K3];
__device__ __nv_bfloat16 g_woc[(size_t)DMODEL * K3];

// split-bf16 copies for attention (rope applied to Q, K)
__device__ __nv_bfloat16 g_qh[(size_t)MROWS * QE];
__device__ __nv_bfloat16 g_ql[(size_t)MROWS * QE];
__device__ __nv_bfloat16 g_kh[(size_t)MROWS * KVE];
__device__ __nv_bfloat16 g_kl[(size_t)MROWS * KVE];
__device__ __nv_bfloat16 g_vh[(size_t)MROWS * KVE];
__device__ __nv_bfloat16 g_vl[(size_t)MROWS * KVE];

// ---------------- helpers ----------------
__device__ __forceinline__ uint32_t smem_u32(const void* p) {
    uint32_t a;
    asm("{ .reg .u64 t; cvta.to.shared.u64 t, %1; cvt.u32.u64 %0, t; }"
        : "=r"(a) : "l"(p));
    return a;
}
__device__ __forceinline__ void cp16(uint32_t dst, const void* src) {
    asm volatile("cp.async.cg.shared.global [%0], [%1], 16;"
                 :: "r"(dst), "l"(src));
}
__device__ __forceinline__ void ldsm_x4(uint32_t* r, uint32_t addr) {
    asm volatile("ldmatrix.sync.aligned.m8n8.x4.shared.b16 {%0,%1,%2,%3}, [%4];"
                 : "=r"(r[0]), "=r"(r[1]), "=r"(r[2]), "=r"(r[3]) : "r"(addr));
}
__device__ __forceinline__ void ldsm_x4_t(uint32_t* r, uint32_t addr) {
    asm volatile("ldmatrix.sync.aligned.m8n8.x4.trans.shared.b16 {%0,%1,%2,%3}, [%4];"
                 : "=r"(r[0]), "=r"(r[1]), "=r"(r[2]), "=r"(r[3]) : "r"(addr));
}
__device__ __forceinline__ void mma_bf16(float* d, const uint32_t* a,
                                         const uint32_t* b) {
    asm volatile(
        "mma.sync.aligned.m16n8k16.row.col.f32.bf16.bf16.f32 "
        "{%0,%1,%2,%3}, {%4,%5,%6,%7}, {%8,%9}, {%0,%1,%2,%3};"
        : "+f"(d[0]), "+f"(d[1]), "+f"(d[2]), "+f"(d[3])
        : "r"(a[0]), "r"(a[1]), "r"(a[2]), "r"(a[3]), "r"(b[0]), "r"(b[1]));
}
__device__ __forceinline__ uint32_t pack_bf16(float lo, float hi) {
    uint32_t r;
    asm("cvt.rn.bf16x2.f32 %0, %1, %2;" : "=r"(r) : "f"(hi), "f"(lo));
    return r;
}
// split pair (x low, y high) into hi/lo bf16x2
__device__ __forceinline__ void split2(float x, float y, uint32_t& hi, uint32_t& lo) {
    uint32_t h = pack_bf16(x, y);
    __nv_bfloat162 hb = *reinterpret_cast<__nv_bfloat162*>(&h);
    lo = pack_bf16(x - __bfloat162float(hb.x), y - __bfloat162float(hb.y));
    hi = h;
}

// ============================================================================
// split-bf16 conversion for GEMM operands
// ============================================================================
__global__ __launch_bounds__(256)
void convert_split(const float4* __restrict__ src, __nv_bfloat16* __restrict__ dst,
                   size_t total4, int act)
{
    size_t i = (size_t)blockIdx.x * blockDim.x + threadIdx.x;
    if (i >= total4) return;
    float4 v = src[i];
    size_t e = i * 4;
    size_t r = e >> 11;
    int    c = (int)(e & 2047);
    float xs[4] = {v.x, v.y, v.z, v.w};
    __nv_bfloat16* d = dst + r * (size_t)K3 + c;
    #pragma unroll
    for (int j = 0; j < 4; j++) {
        __nv_bfloat16 h = __float2bfloat16(xs[j]);
        __nv_bfloat16 l = __float2bfloat16(xs[j] - __bfloat162float(h));
        d[j]              = h;
        d[DMODEL + j]     = act ? l : h;
        d[2 * DMODEL + j] = act ? h : l;
    }
}

// ============================================================================
// bf16 mma.sync GEMM (unchanged from round 3, passing)
// ============================================================================
constexpr int GSTRIDE = 40;
constexpr int GBUF    = 128 * GSTRIDE * 2;
constexpr int GEMM_SMEM = 4 * GBUF;

__global__ __launch_bounds__(256)
void bgemm(const __nv_bfloat16* __restrict__ A,
           const __nv_bfloat16* __restrict__ B,
           float* __restrict__ C, int N)
{
    extern __shared__ char sm[];
    const uint32_t sA = smem_u32(sm);
    const uint32_t sB = sA + 2 * GBUF;

    const int tid = threadIdx.x;
    const int wid = tid >> 5;
    const int lane = tid & 31;
    const int m0 = blockIdx.y * 128;
    const int n0 = blockIdx.x * 128;
    const int wm = (wid >> 2) * 64;
    const int wn = (wid & 3) * 32;

    const __nv_bfloat16* Abase = A + (size_t)m0 * K3;
    const __nv_bfloat16* Bbase = B + (size_t)n0 * K3;

    const int grp = lane >> 3, lr = lane & 7;
    uint32_t aaddr[4], baddr[2];
    #pragma unroll
    for (int mf = 0; mf < 4; mf++) {
        int row = wm + mf * 16 + (grp & 1) * 8 + lr;
        aaddr[mf] = sA + row * (GSTRIDE * 2) + (grp >> 1) * 16;
    }
    #pragma unroll
    for (int nf2 = 0; nf2 < 2; nf2++) {
        int row = wn + nf2 * 16 + (grp >> 1) * 8 + lr;
        baddr[nf2] = sB + row * (GSTRIDE * 2) + (grp & 1) * 16;
    }

    float acc[4][4][4];
    #pragma unroll
    for (int mf = 0; mf < 4; mf++)
        #pragma unroll
        for (int nf = 0; nf < 4; nf++)
            #pragma unroll
            for (int e = 0; e < 4; e++) acc[mf][nf][e] = 0.f;

    auto issue = [&](int c) {
        const int buf = c & 1;
        const __nv_bfloat16* Ag = Abase + c * 32;
        const __nv_bfloat16* Bg = Bbase + c * 32;
        #pragma unroll
        for (int t = 0; t < 2; t++) {
            int i = tid + t * 256;
            int row = i >> 2, seg = i & 3;
            cp16(sA + buf * GBUF + row * (GSTRIDE * 2) + seg * 16,
                 Ag + (size_t)row * K3 + seg * 8);
        }
        #pragma unroll
        for (int t = 0; t < 2; t++) {
            int i = tid + t * 256;
            int row = i >> 2, seg = i & 3;
            cp16(sB + buf * GBUF + row * (GSTRIDE * 2) + seg * 16,
                 Bg + (size_t)row * K3 + seg * 8);
        }
    };

    issue(0);
    asm volatile("cp.async.commit_group;" ::: "memory");

    for (int c = 0; c < NCHUNK; c++) {
        asm volatile("cp.async.wait_group 0;" ::: "memory");
        __syncthreads();
        if (c + 1 < NCHUNK) {
            issue(c + 1);
            asm volatile("cp.async.commit_group;" ::: "memory");
        }
        const uint32_t boff = (c & 1) * GBUF;

        #pragma unroll
        for (int s = 0; s < 2; s++) {
            const uint32_t koff = boff + s * 32;
            uint32_t ar[4][4], br[2][4];
            #pragma unroll
            for (int mf = 0; mf < 4; mf++) ldsm_x4(ar[mf], aaddr[mf] + koff);
            #pragma unroll
            for (int nf2 = 0; nf2 < 2; nf2++) ldsm_x4(br[nf2], baddr[nf2] + koff);
            #pragma unroll
            for (int mf = 0; mf < 4; mf++)
                #pragma unroll
                for (int nf = 0; nf < 4; nf++)
                    mma_bf16(acc[mf][nf], ar[mf], &br[nf >> 1][(nf & 1) * 2]);
        }
        __syncthreads();
    }

    const int lr4 = lane >> 2, lc2 = (lane & 3) * 2;
    #pragma unroll
    for (int mf = 0; mf < 4; mf++) {
        int r = m0 + wm + mf * 16 + lr4;
        #pragma unroll
        for (int nf = 0; nf < 4; nf++) {
            int cc = n0 + wn + nf * 8 + lc2;
            *(float2*)(C + (size_t)r * N + cc) =
                make_float2(acc[mf][nf][0], acc[mf][nf][1]);
            *(float2*)(C + (size_t)(r + 8) * N + cc) =
                make_float2(acc[mf][nf][2], acc[mf][nf][3]);
        }
    }
}

// ============================================================================
// RoPE + hi/lo bf16 split (for attention Q, K)
// ============================================================================
__global__ __launch_bounds__(256)
void rope_split(const float* __restrict__ src,
                const float* __restrict__ cs, const float* __restrict__ sn,
                __nv_bfloat16* __restrict__ dh, __nv_bfloat16* __restrict__ dl,
                int heads, int total_pairs)
{
    int idx = blockIdx.x * blockDim.x + threadIdx.x;
    if (idx >= total_pairs) return;
    int p    = idx & 63;
    int rest = idx >> 6;
    int s    = (rest / heads) & (SEQ - 1);

    float c  = cs[s * 64 + p];
    float si = sn[s * 64 + p];
    const float* base = src + (size_t)rest * HD + 2 * p;
    float e = base[0], o = base[1];
    float re = e * c - o * si;
    float ro = e * si + o * c;

    size_t pos = (size_t)rest * HD + 2 * p;
    __nv_bfloat16 h0 = __float2bfloat16(re);
    __nv_bfloat16 h1 = __float2bfloat16(ro);
    dh[pos]     = h0;
    dh[pos + 1] = h1;
    dl[pos]     = __float2bfloat16(re - __bfloat162float(h0));
    dl[pos + 1] = __float2bfloat16(ro - __bfloat162float(h1));
}

// plain hi/lo split (for V)
__global__ __launch_bounds__(256)
void hl_split(const float4* __restrict__ src,
              __nv_bfloat16* __restrict__ dh, __nv_bfloat16* __restrict__ dl,
              size_t total4)
{
    size_t i = (size_t)blockIdx.x * blockDim.x + threadIdx.x;
    if (i >= total4) return;
    float4 v = src[i];
    float xs[4] = {v.x, v.y, v.z, v.w};
    size_t e = i * 4;
    #pragma unroll
    for (int j = 0; j < 4; j++) {
        __nv_bfloat16 h = __float2bfloat16(xs[j]);
        dh[e + j] = h;
        dl[e + j] = __float2bfloat16(xs[j] - __bfloat162float(h));
    }
}

// ============================================================================
// Tensor-core causal flash attention, split-bf16 (Br=128, Bc=64)
// 8 warps; warp w owns q-rows [16w,16w+16). Double-buffered K/V via cp.async.
// ============================================================================
constexpr int ATT_STRIDE = 136;              // bf16 per smem row (padded)
constexpr int ROWB  = ATT_STRIDE * 2;        // 272 bytes
constexpr int QTILE = 128 * ROWB;            // 34816
constexpr int KTILE = 64 * ROWB;             // 17408
constexpr int ATT_SMEM = 2 * QTILE + 2 * 4 * KTILE;  // 208896

__global__ __launch_bounds__(256)
void attn_mma(const __nv_bfloat16* __restrict__ Qh, const __nv_bfloat16* __restrict__ Ql,
              const __nv_bfloat16* __restrict__ Kh, const __nv_bfloat16* __restrict__ Kl,
              const __nv_bfloat16* __restrict__ Vh, const __nv_bfloat16* __restrict__ Vl,
              float* __restrict__ Og)
{
    extern __shared__ char sm[];
    const uint32_t sb = smem_u32(sm);

    const int qb = gridDim.x - 1 - blockIdx.x;   // heavy blocks first
    const int h  = blockIdx.y;
    const int b  = blockIdx.z;
    const int kh = h >> 2;
    const int tid = threadIdx.x;
    const int wid = tid >> 5;
    const int lane = tid & 31;
    const int q0 = qb * 128;
    const int nkb = q0 / 64 + 2;

    // ---- Q tile loads (hi + lo) ----
    {
        const size_t qrow = ((size_t)(b * SEQ + q0) * NH + h) * HD;
        for (int i = tid; i < 2048; i += 256) {
            int r = i >> 4, ch = i & 15;
            size_t g = qrow + (size_t)r * NH * HD + ch * 8;
            uint32_t so = r * ROWB + ch * 16;
            cp16(sb + so, Qh + g);
            cp16(sb + QTILE + so, Ql + g);
        }
    }

    auto issue_kv = [&](int kb) {
        const uint32_t st = sb + 2 * QTILE + (kb & 1) * (4 * KTILE);
        const size_t kvrow = ((size_t)(b * SEQ + kb * 64) * NKV + kh) * HD;
        for (int i = tid; i < 1024; i += 256) {
            int r = i >> 4, ch = i & 15;
            size_t g = kvrow + (size_t)r * NKV * HD + ch * 8;
            uint32_t so = r * ROWB + ch * 16;
            cp16(st + so,             Kh + g);
            cp16(st + KTILE + so,     Kl + g);
            cp16(st + 2 * KTILE + so, Vh + g);
            cp16(st + 3 * KTILE + so, Vl + g);
        }
    };

    issue_kv(0);
    asm volatile("cp.async.commit_group;" ::: "memory");

    // ldmatrix lane bases
    const int grp = lane >> 3, lr = lane & 7;
    const uint32_t qa_h = sb + (wid * 16 + (grp & 1) * 8 + lr) * ROWB + (grp >> 1) * 16;
    const uint32_t qa_l = qa_h + QTILE;
    const uint32_t kboff = ((grp >> 1) * 8 + lr) * ROWB + (grp & 1) * 16;   // K non-trans
    const uint32_t vboff = ((grp & 1) * 8 + lr) * ROWB + (grp >> 1) * 16;   // V trans

    float m_[2] = {-1e30f, -1e30f};
    float l_[2] = {0.f, 0.f};
    float of[16][4];
    #pragma unroll
    for (int nf = 0; nf < 16; nf++)
        #pragma unroll
        for (int e = 0; e < 4; e++) of[nf][e] = 0.f;

    const float scale = 0.08838834764831845f;
    const int rbase = q0 + wid * 16 + (lane >> 2);

    for (int kb = 0; kb < nkb; kb++) {
        if (kb + 1 < nkb) {
            issue_kv(kb + 1);
            asm volatile("cp.async.commit_group;" ::: "memory");
            asm volatile("cp.async.wait_group 1;" ::: "memory");
        } else {
            asm volatile("cp.async.wait_group 0;" ::: "memory");
        }
        __syncthreads();

        const uint32_t st = sb + 2 * QTILE + (kb & 1) * (4 * KTILE);

        // ---- S = Q K^T, 3-term split ----
        float sf[8][4];
        #pragma unroll
        for (int f = 0; f < 8; f++)
            #pragma unroll
            for (int e = 0; e < 4; e++) sf[f][e] = 0.f;

        #pragma unroll
        for (int ks = 0; ks < 8; ks++) {
            uint32_t ah[4], al[4];
            ldsm_x4(ah, qa_h + ks * 32);
            ldsm_x4(al, qa_l + ks * 32);
            #pragma unroll
            for (int nb = 0; nb < 4; nb++) {
                uint32_t bh[4], bl[4];
                ldsm_x4(bh, st + kboff + nb * 16 * ROWB + ks * 32);
                ldsm_x4(bl, st + KTILE + kboff + nb * 16 * ROWB + ks * 32);
                mma_bf16(sf[2 * nb],     ah, bh);
                mma_bf16(sf[2 * nb + 1], ah, bh + 2);
                mma_bf16(sf[2 * nb],     al, bh);
                mma_bf16(sf[2 * nb + 1], al, bh + 2);
                mma_bf16(sf[2 * nb],     ah, bl);
                mma_bf16(sf[2 * nb + 1], ah, bl + 2);
            }
        }

        // ---- scale + mask + online softmax ----
        float mx[2] = {-1e30f, -1e30f};
        #pragma unroll
        for (int f = 0; f < 8; f++)
            #pragma unroll
            for (int e = 0; e < 4; e++) {
                float v = sf[f][e] * scale;
                int col = kb * 64 + f * 8 + ((lane & 3) << 1) + (e & 1);
                int row = rbase + ((e & 2) << 2);
                v = (col > row) ? -1e30f : v;
                sf[f][e] = v;
                mx[e >> 1] = fmaxf(mx[e >> 1], v);
            }
        #pragma unroll
        for (int e = 0; e < 2; e++) {
            mx[e] = fmaxf(mx[e], __shfl_xor_sync(0xffffffffu, mx[e], 1));
            mx[e] = fmaxf(mx[e], __shfl_xor_sync(0xffffffffu, mx[e], 2));
        }
        float mn[2], alp[2], rs[2] = {0.f, 0.f};
        #pragma unroll
        for (int e = 0; e < 2; e++) {
            mn[e]  = fmaxf(m_[e], mx[e]);
            alp[e] = __expf(m_[e] - mn[e]);
            m_[e]  = mn[e];
        }
        #pragma unroll
        for (int f = 0; f < 8; f++)
            #pragma unroll
            for (int e = 0; e < 4; e++) {
                float p = __expf(sf[f][e] - mn[e >> 1]);
                sf[f][e] = p;
                rs[e >> 1] += p;
            }
        #pragma unroll
        for (int e = 0; e < 2; e++) {
            rs[e] += __shfl_xor_sync(0xffffffffu, rs[e], 1);
            rs[e] += __shfl_xor_sync(0xffffffffu, rs[e], 2);
            l_[e] = l_[e] * alp[e] + rs[e];
        }
        #pragma unroll
        for (int nf = 0; nf < 16; nf++) {
            of[nf][0] *= alp[0]; of[nf][1] *= alp[0];
            of[nf][2] *= alp[1]; of[nf][3] *= alp[1];
        }

        // ---- O += P V, 3-term split ----
        #pragma unroll
        for (int ks = 0; ks < 4; ks++) {
            uint32_t ph[4], pl[4];
            split2(sf[2 * ks][0],     sf[2 * ks][1],     ph[0], pl[0]);
            split2(sf[2 * ks][2],     sf[2 * ks][3],     ph[1], pl[1]);
            split2(sf[2 * ks + 1][0], sf[2 * ks + 1][1], ph[2], pl[2]);
            split2(sf[2 * ks + 1][2], sf[2 * ks + 1][3], ph[3], pl[3]);
            #pragma unroll
            for (int nb = 0; nb < 8; nb++) {
                uint32_t vh4[4], vl4[4];
                ldsm_x4_t(vh4, st + 2 * KTILE + vboff + ks * 16 * ROWB + nb * 32);
                ldsm_x4_t(vl4, st + 3 * KTILE + vboff + ks * 16 * ROWB + nb * 32);
                mma_bf16(of[2 * nb],     ph, vh4);
                mma_bf16(of[2 * nb + 1], ph, vh4 + 2);
                mma_bf16(of[2 * nb],     pl, vh4);
                mma_bf16(of[2 * nb + 1], pl, vh4 + 2);
                mma_bf16(of[2 * nb],     ph, vl4);
                mma_bf16(of[2 * nb + 1], ph, vl4 + 2);
            }
        }
        __syncthreads();
    }

    // ---- epilogue ----
    float inv0 = 1.f / l_[0], inv1 = 1.f / l_[1];
    size_t base0 = ((size_t)(b * SEQ + rbase) * NH + h) * HD + ((lane & 3) << 1);
    size_t base1 = base0 + (size_t)8 * NH * HD;
    #pragma unroll
    for (int nf = 0; nf < 16; nf++) {
        *(float2*)(Og + base0 + nf * 8) = make_float2(of[nf][0] * inv0, of[nf][1] * inv0);
        *(float2*)(Og + base1 + nf * 8) = make_float2(of[nf][2] * inv1, of[nf][3] * inv1);
    }
}

// ============================================================================
// host launcher
// ============================================================================
extern "C" void kernel_launch(void* const* d_in, const int* in_sizes, int n_in,
                              void* d_out, int out_size)
{
    const float* x  = (const float*)d_in[0];
    const float* fc = (const float*)d_in[1];
    const float* fs = (const float*)d_in[2];
    const float* wq = (const float*)d_in[4];
    const float* wk = (const float*)d_in[5];
    const float* wv = (const float*)d_in[6];
    const float* wo = (const float*)d_in[7];
    float* out = (float*)d_out;

    float *q, *k, *v, *ao;
    __nv_bfloat16 *xc, *aoc, *wqc, *wkc, *wvc, *woc;
    __nv_bfloat16 *qh, *ql, *kh, *kl, *vh, *vl;
    cudaGetSymbolAddress((void**)&q,   g_q);
    cudaGetSymbolAddress((void**)&k,   g_k);
    cudaGetSymbolAddress((void**)&v,   g_v);
    cudaGetSymbolAddress((void**)&ao,  g_ao);
    cudaGetSymbolAddress((void**)&xc,  g_xc);
    cudaGetSymbolAddress((void**)&aoc, g_aoc);
    cudaGetSymbolAddress((void**)&wqc, g_wqc);
    cudaGetSymbolAddress((void**)&wkc, g_wkc);
    cudaGetSymbolAddress((void**)&wvc, g_wvc);
    cudaGetSymbolAddress((void**)&woc, g_woc);
    cudaGetSymbolAddress((void**)&qh,  g_qh);
    cudaGetSymbolAddress((void**)&ql,  g_ql);
    cudaGetSymbolAddress((void**)&kh,  g_kh);
    cudaGetSymbolAddress((void**)&kl,  g_kl);
    cudaGetSymbolAddress((void**)&vh,  g_vh);
    cudaGetSymbolAddress((void**)&vl,  g_vl);

    cudaFuncSetAttribute(bgemm, cudaFuncAttributeMaxDynamicSharedMemorySize,
                         GEMM_SMEM);
    cudaFuncSetAttribute(attn_mma, cudaFuncAttributeMaxDynamicSharedMemorySize,
                         ATT_SMEM);

    // ---- split-bf16 conversions for projections ----
    {
        size_t t4;
        t4 = (size_t)MROWS * DMODEL / 4;
        convert_split<<<(unsigned)((t4 + 255) / 256), 256>>>((const float4*)x,  xc,  t4, 1);
        t4 = (size_t)QE * DMODEL / 4;
        convert_split<<<(unsigned)((t4 + 255) / 256), 256>>>((const float4*)wq, wqc, t4, 0);
        t4 = (size_t)KVE * DMODEL / 4;
        convert_split<<<(unsigned)((t4 + 255) / 256), 256>>>((const float4*)wk, wkc, t4, 0);
        convert_split<<<(unsigned)((t4 + 255) / 256), 256>>>((const float4*)wv, wvc, t4, 0);
        t4 = (size_t)DMODEL * DMODEL / 4;
        convert_split<<<(unsigned)((t4 + 255) / 256), 256>>>((const float4*)wo, woc, t4, 0);
    }

    // ---- QKV projections (HMMA) ----
    bgemm<<<dim3(QE  / 128, MROWS / 128), 256, GEMM_SMEM>>>(xc, wqc, q, QE);
    bgemm<<<dim3(KVE / 128, MROWS / 128), 256, GEMM_SMEM>>>(xc, wkc, k, KVE);
    bgemm<<<dim3(KVE / 128, MROWS / 128), 256, GEMM_SMEM>>>(xc, wvc, v, KVE);

    // ---- RoPE + hi/lo splits for attention operands ----
    {
        int tp_q = MROWS * NH  * (HD / 2);
        int tp_k = MROWS * NKV * (HD / 2);
        rope_split<<<(tp_q + 255) / 256, 256>>>(q, fc, fs, qh, ql, NH,  tp_q);
        rope_split<<<(tp_k + 255) / 256, 256>>>(k, fc, fs, kh, kl, NKV, tp_k);
        size_t t4 = (size_t)MROWS * KVE / 4;
        hl_split<<<(unsigned)((t4 + 255) / 256), 256>>>((const float4*)v, vh, vl, t4);
    }

    // ---- tensor-core causal attention ----
    attn_mma<<<dim3(SEQ / 128, NH, BB), 256, ATT_SMEM>>>(qh, ql, kh, kl, vh, vl, ao);

    // ---- output projection ----
    {
        size_t t4 = (size_t)MROWS * DMODEL / 4;
        convert_split<<<(unsigned)((t4 + 255) / 256), 256>>>((const float4*)ao, aoc, t4, 1);
    }
    bgemm<<<dim3(DMODEL / 128, MROWS / 128), 256, GEMM_SMEM>>>(aoc, woc, out, DMODEL);
}

// round 5
// speedup vs baseline: 6.4296x; 1.6350x over previous
#include <cuda_runtime.h>
#include <cuda_fp16.h>
#include <math.h>
#include <cstdint>

// ---------------- problem constants ----------------
constexpr int BB     = 2;
constexpr int SEQ    = 2048;
constexpr int DMODEL = 2048;
constexpr int NH     = 16;
constexpr int NKV    = 4;
constexpr int HD     = 128;
constexpr int MROWS  = BB * SEQ;     // 4096
constexpr int QE     = NH * HD;      // 2048
constexpr int KVE    = NKV * HD;     // 512
constexpr int K2     = 4096;         // 2-term fp16 split K
constexpr int NCH2   = 128;          // chunks of 32

// ---------------- scratch ----------------
__device__ float g_q [(size_t)MROWS * QE];
__device__ float g_k [(size_t)MROWS * KVE];
__device__ float g_v [(size_t)MROWS * KVE];
__device__ float g_ao[(size_t)MROWS * QE];

__device__ __half g_x2 [(size_t)MROWS * K2];    // [xh | xl]
__device__ __half g_ao2[(size_t)MROWS * K2];
__device__ __half g_wqh[(size_t)QE     * DMODEL];
__device__ __half g_wkh[(size_t)KVE    * DMODEL];
__device__ __half g_wvh[(size_t)KVE    * DMODEL];
__device__ __half g_woh[(size_t)DMODEL * DMODEL];

__device__ __half g_qh2[(size_t)MROWS * QE];
__device__ __half g_ql2[(size_t)MROWS * QE];
__device__ __half g_kh2[(size_t)MROWS * KVE];
__device__ __half g_vh2[(size_t)MROWS * KVE];

// ---------------- helpers ----------------
__device__ __forceinline__ uint32_t smem_u32(const void* p) {
    uint32_t a;
    asm("{ .reg .u64 t; cvta.to.shared.u64 t, %1; cvt.u32.u64 %0, t; }"
        : "=r"(a) : "l"(p));
    return a;
}
__device__ __forceinline__ void cp16(uint32_t dst, const void* src) {
    asm volatile("cp.async.cg.shared.global [%0], [%1], 16;"
                 :: "r"(dst), "l"(src));
}
__device__ __forceinline__ void ldsm_x4(uint32_t* r, uint32_t addr) {
    asm volatile("ldmatrix.sync.aligned.m8n8.x4.shared.b16 {%0,%1,%2,%3}, [%4];"
                 : "=r"(r[0]), "=r"(r[1]), "=r"(r[2]), "=r"(r[3]) : "r"(addr));
}
__device__ __forceinline__ void ldsm_x4_t(uint32_t* r, uint32_t addr) {
    asm volatile("ldmatrix.sync.aligned.m8n8.x4.trans.shared.b16 {%0,%1,%2,%3}, [%4];"
                 : "=r"(r[0]), "=r"(r[1]), "=r"(r[2]), "=r"(r[3]) : "r"(addr));
}
__device__ __forceinline__ void mma_f16(float* d, const uint32_t* a,
                                        const uint32_t* b) {
    asm volatile(
        "mma.sync.aligned.m16n8k16.row.col.f32.f16.f16.f32 "
        "{%0,%1,%2,%3}, {%4,%5,%6,%7}, {%8,%9}, {%0,%1,%2,%3};"
        : "+f"(d[0]), "+f"(d[1]), "+f"(d[2]), "+f"(d[3])
        : "r"(a[0]), "r"(a[1]), "r"(a[2]), "r"(a[3]), "r"(b[0]), "r"(b[1]));
}
__device__ __forceinline__ uint32_t pack_f16(float lo, float hi) {
    uint32_t r;
    asm("cvt.rn.f16x2.f32 %0, %1, %2;" : "=r"(r) : "f"(hi), "f"(lo));
    return r;
}
__device__ __forceinline__ void split2h(float x, float y, uint32_t& hi, uint32_t& lo) {
    uint32_t h = pack_f16(x, y);
    __half2 hb = *reinterpret_cast<__half2*>(&h);
    lo = pack_f16(x - __half2float(hb.x), y - __half2float(hb.y));
    hi = h;
}

// ============================================================================
// converts
// ============================================================================
// x (fp32, K=2048 rows) -> [hi | lo] fp16 at row stride 4096
__global__ __launch_bounds__(256)
void convert_2h(const float4* __restrict__ src, __half* __restrict__ dst,
                size_t total4)
{
    size_t i = (size_t)blockIdx.x * blockDim.x + threadIdx.x;
    if (i >= total4) return;
    float4 v = src[i];
    size_t e = i * 4;
    size_t r = e >> 11;
    int    c = (int)(e & 2047);
    float xs[4] = {v.x, v.y, v.z, v.w};
    __half* d = dst + r * (size_t)K2 + c;
    #pragma unroll
    for (int j = 0; j < 4; j++) {
        __half h = __float2half(xs[j]);
        d[j]          = h;
        d[DMODEL + j] = __float2half(xs[j] - __half2float(h));
    }
}
// plain fp32 -> fp16
__global__ __launch_bounds__(256)
void convert_h(const float4* __restrict__ src, __half* __restrict__ dst,
               size_t total4)
{
    size_t i = (size_t)blockIdx.x * blockDim.x + threadIdx.x;
    if (i >= total4) return;
    float4 v = src[i];
    size_t e = i * 4;
    dst[e]     = __float2half(v.x);
    dst[e + 1] = __float2half(v.y);
    dst[e + 2] = __float2half(v.z);
    dst[e + 3] = __float2half(v.w);
}

// ============================================================================
// fp16 2-term mma.sync GEMM: C[M,N] = [Ah|Al][M,4096] * Bh[N,2048]^T
// 128x128 tile, BK=32, 8 warps, 4-stage cp.async pipeline
// ============================================================================
constexpr int HSTR   = 40;                 // halves per smem row
constexpr int HROWB  = 80;                 // bytes per row
constexpr int GTILE  = 128 * HROWB;        // 10240 B
constexpr int GSTAGE = 2 * GTILE;          // A + B
constexpr int GEMM16_SMEM = 4 * GSTAGE;    // 81920

__global__ __launch_bounds__(256, 2)
void bgemm16(const __half* __restrict__ A,
             const __half* __restrict__ B0, const __half* __restrict__ B1,
             float* __restrict__ C0, float* __restrict__ C1,
             int N0, int N1, int nsplit)
{
    extern __shared__ char sm[];
    const uint32_t sb = smem_u32(sm);

    const int tid = threadIdx.x;
    const int wid = tid >> 5;
    const int lane = tid & 31;
    const int bx = blockIdx.x;
    const int m0 = blockIdx.y * 128;

    const __half* Bw; float* C; int N; int n0;
    if (bx < nsplit) { Bw = B0; C = C0; N = N0; n0 = bx * 128; }
    else             { Bw = B1; C = C1; N = N1; n0 = (bx - nsplit) * 128; }

    const int wm = (wid >> 2) * 64;
    const int wn = (wid & 3) * 32;

    const __half* Abase = A  + (size_t)m0 * K2;
    const __half* Bbase = Bw + (size_t)n0 * DMODEL;

    const int grp = lane >> 3, lr = lane & 7;
    uint32_t aoff[4], boff[2];
    #pragma unroll
    for (int mf = 0; mf < 4; mf++)
        aoff[mf] = (wm + mf * 16 + (grp & 1) * 8 + lr) * HROWB + (grp >> 1) * 16;
    #pragma unroll
    for (int nf2 = 0; nf2 < 2; nf2++)
        boff[nf2] = GTILE + (wn + nf2 * 16 + (grp >> 1) * 8 + lr) * HROWB
                  + (grp & 1) * 16;

    float acc[4][4][4];
    #pragma unroll
    for (int mf = 0; mf < 4; mf++)
        #pragma unroll
        for (int nf = 0; nf < 4; nf++)
            #pragma unroll
            for (int e = 0; e < 4; e++) acc[mf][nf][e] = 0.f;

    auto issue = [&](int c) {
        if (c >= NCH2) return;
        const uint32_t st = sb + (c & 3) * GSTAGE;
        const __half* Ag = Abase + c * 32;
        const __half* Bg = Bbase + (c & 63) * 32;
        #pragma unroll
        for (int t = 0; t < 2; t++) {
            int i = tid + t * 256;
            int row = i >> 2, seg = i & 3;
            cp16(st + row * HROWB + seg * 16, Ag + (size_t)row * K2 + seg * 8);
        }
        #pragma unroll
        for (int t = 0; t < 2; t++) {
            int i = tid + t * 256;
            int row = i >> 2, seg = i & 3;
            cp16(st + GTILE + row * HROWB + seg * 16,
                 Bg + (size_t)row * DMODEL + seg * 8);
        }
    };

    issue(0); asm volatile("cp.async.commit_group;" ::: "memory");
    issue(1); asm volatile("cp.async.commit_group;" ::: "memory");
    issue(2); asm volatile("cp.async.commit_group;" ::: "memory");

    for (int c = 0; c < NCH2; c++) {
        asm volatile("cp.async.wait_group 2;" ::: "memory");
        __syncthreads();
        issue(c + 3);
        asm volatile("cp.async.commit_group;" ::: "memory");

        const uint32_t st = sb + (c & 3) * GSTAGE;
        #pragma unroll
        for (int s = 0; s < 2; s++) {
            const uint32_t koff = s * 32;
            uint32_t ar[4][4], br[2][4];
            #pragma unroll
            for (int mf = 0; mf < 4; mf++) ldsm_x4(ar[mf], st + aoff[mf] + koff);
            #pragma unroll
            for (int nf2 = 0; nf2 < 2; nf2++) ldsm_x4(br[nf2], st + boff[nf2] + koff);
            #pragma unroll
            for (int mf = 0; mf < 4; mf++)
                #pragma unroll
                for (int nf = 0; nf < 4; nf++)
                    mma_f16(acc[mf][nf], ar[mf], &br[nf >> 1][(nf & 1) * 2]);
        }
    }

    const int lr4 = lane >> 2, lc2 = (lane & 3) * 2;
    #pragma unroll
    for (int mf = 0; mf < 4; mf++) {
        int r = m0 + wm + mf * 16 + lr4;
        #pragma unroll
        for (int nf = 0; nf < 4; nf++) {
            int cc = n0 + wn + nf * 8 + lc2;
            *(float2*)(C + (size_t)r * N + cc) =
                make_float2(acc[mf][nf][0], acc[mf][nf][1]);
            *(float2*)(C + (size_t)(r + 8) * N + cc) =
                make_float2(acc[mf][nf][2], acc[mf][nf][3]);
        }
    }
}

// ============================================================================
// RoPE + fp16 split (lo optional)
// ============================================================================
__global__ __launch_bounds__(256)
void rope_split_h(const float* __restrict__ src,
                  const float* __restrict__ cs, const float* __restrict__ sn,
                  __half* __restrict__ dh, __half* __restrict__ dl,
                  int heads, int total_pairs)
{
    int idx = blockIdx.x * blockDim.x + threadIdx.x;
    if (idx >= total_pairs) return;
    int p    = idx & 63;
    int rest = idx >> 6;
    int s    = (rest / heads) & (SEQ - 1);

    float c  = cs[s * 64 + p];
    float si = sn[s * 64 + p];
    const float* base = src + (size_t)rest * HD + 2 * p;
    float e = base[0], o = base[1];
    float re = e * c - o * si;
    float ro = e * si + o * c;

    size_t pos = (size_t)rest * HD + 2 * p;
    __half h0 = __float2half(re);
    __half h1 = __float2half(ro);
    dh[pos]     = h0;
    dh[pos + 1] = h1;
    if (dl) {
        dl[pos]     = __float2half(re - __half2float(h0));
        dl[pos + 1] = __float2half(ro - __half2float(h1));
    }
}

// ============================================================================
// fp16 2-term tensor-core causal flash attention (Br=128, Bc=64)
// ============================================================================
constexpr int ATT_STRIDE = 136;              // halves per row
constexpr int ROWB  = ATT_STRIDE * 2;        // 272 B
constexpr int QTILE = 128 * ROWB;            // 34816
constexpr int KTILE = 64 * ROWB;             // 17408
constexpr int ATT_SMEM = 2 * QTILE + 2 * 2 * KTILE;  // 139264

__global__ __launch_bounds__(256)
void attn_mma(const __half* __restrict__ Qh, const __half* __restrict__ Ql,
              const __half* __restrict__ Kh, const __half* __restrict__ Vh,
              float* __restrict__ Og)
{
    extern __shared__ char sm[];
    const uint32_t sb = smem_u32(sm);

    const int qb = gridDim.x - 1 - blockIdx.x;
    const int h  = blockIdx.y;
    const int b  = blockIdx.z;
    const int kh = h >> 2;
    const int tid = threadIdx.x;
    const int wid = tid >> 5;
    const int lane = tid & 31;
    const int q0 = qb * 128;
    const int nkb = q0 / 64 + 2;

    // Q tile loads (hi + lo)
    {
        const size_t qrow = ((size_t)(b * SEQ + q0) * NH + h) * HD;
        for (int i = tid; i < 2048; i += 256) {
            int r = i >> 4, ch = i & 15;
            size_t g = qrow + (size_t)r * NH * HD + ch * 8;
            uint32_t so = r * ROWB + ch * 16;
            cp16(sb + so, Qh + g);
            cp16(sb + QTILE + so, Ql + g);
        }
    }

    auto issue_kv = [&](int kb) {
        const uint32_t st = sb + 2 * QTILE + (kb & 1) * (2 * KTILE);
        const size_t kvrow = ((size_t)(b * SEQ + kb * 64) * NKV + kh) * HD;
        for (int i = tid; i < 1024; i += 256) {
            int r = i >> 4, ch = i & 15;
            size_t g = kvrow + (size_t)r * NKV * HD + ch * 8;
            uint32_t so = r * ROWB + ch * 16;
            cp16(st + so,         Kh + g);
            cp16(st + KTILE + so, Vh + g);
        }
    };

    issue_kv(0);
    asm volatile("cp.async.commit_group;" ::: "memory");

    const int grp = lane >> 3, lr = lane & 7;
    const uint32_t qa_h = sb + (wid * 16 + (grp & 1) * 8 + lr) * ROWB + (grp >> 1) * 16;
    const uint32_t qa_l = qa_h + QTILE;
    const uint32_t kboff = ((grp >> 1) * 8 + lr) * ROWB + (grp & 1) * 16;
    const uint32_t vboff = ((grp & 1) * 8 + lr) * ROWB + (grp >> 1) * 16;

    float m_[2] = {-1e30f, -1e30f};
    float l_[2] = {0.f, 0.f};
    float of[16][4];
    #pragma unroll
    for (int nf = 0; nf < 16; nf++)
        #pragma unroll
        for (int e = 0; e < 4; e++) of[nf][e] = 0.f;

    const float scale = 0.08838834764831845f;
    const int rbase = q0 + wid * 16 + (lane >> 2);

    for (int kb = 0; kb < nkb; kb++) {
        if (kb + 1 < nkb) {
            issue_kv(kb + 1);
            asm volatile("cp.async.commit_group;" ::: "memory");
            asm volatile("cp.async.wait_group 1;" ::: "memory");
        } else {
            asm volatile("cp.async.wait_group 0;" ::: "memory");
        }
        __syncthreads();

        const uint32_t st = sb + 2 * QTILE + (kb & 1) * (2 * KTILE);

        // ---- S = Q K^T, 2-term fp16 ----
        float sf[8][4];
        #pragma unroll
        for (int f = 0; f < 8; f++)
            #pragma unroll
            for (int e = 0; e < 4; e++) sf[f][e] = 0.f;

        #pragma unroll
        for (int ks = 0; ks < 8; ks++) {
            uint32_t ah[4], al[4];
            ldsm_x4(ah, qa_h + ks * 32);
            ldsm_x4(al, qa_l + ks * 32);
            #pragma unroll
            for (int nb = 0; nb < 4; nb++) {
                uint32_t bh[4];
                ldsm_x4(bh, st + kboff + nb * 16 * ROWB + ks * 32);
                mma_f16(sf[2 * nb],     ah, bh);
                mma_f16(sf[2 * nb + 1], ah, bh + 2);
                mma_f16(sf[2 * nb],     al, bh);
                mma_f16(sf[2 * nb + 1], al, bh + 2);
            }
        }

        // ---- scale + mask + online softmax ----
        float mx[2] = {-1e30f, -1e30f};
        #pragma unroll
        for (int f = 0; f < 8; f++)
            #pragma unroll
            for (int e = 0; e < 4; e++) {
                float v = sf[f][e] * scale;
                int col = kb * 64 + f * 8 + ((lane & 3) << 1) + (e & 1);
                int row = rbase + ((e & 2) << 2);
                v = (col > row) ? -1e30f : v;
                sf[f][e] = v;
                mx[e >> 1] = fmaxf(mx[e >> 1], v);
            }
        #pragma unroll
        for (int e = 0; e < 2; e++) {
            mx[e] = fmaxf(mx[e], __shfl_xor_sync(0xffffffffu, mx[e], 1));
            mx[e] = fmaxf(mx[e], __shfl_xor_sync(0xffffffffu, mx[e], 2));
        }
        float mn[2], alp[2], rs[2] = {0.f, 0.f};
        #pragma unroll
        for (int e = 0; e < 2; e++) {
            mn[e]  = fmaxf(m_[e], mx[e]);
            alp[e] = __expf(m_[e] - mn[e]);
            m_[e]  = mn[e];
        }
        #pragma unroll
        for (int f = 0; f < 8; f++)
            #pragma unroll
            for (int e = 0; e < 4; e++) {
                float p = __expf(sf[f][e] - mn[e >> 1]);
                sf[f][e] = p;
                rs[e >> 1] += p;
            }
        #pragma unroll
        for (int e = 0; e < 2; e++) {
            rs[e] += __shfl_xor_sync(0xffffffffu, rs[e], 1);
            rs[e] += __shfl_xor_sync(0xffffffffu, rs[e], 2);
            l_[e] = l_[e] * alp[e] + rs[e];
        }
        #pragma unroll
        for (int nf = 0; nf < 16; nf++) {
            of[nf][0] *= alp[0]; of[nf][1] *= alp[0];
            of[nf][2] *= alp[1]; of[nf][3] *= alp[1];
        }

        // ---- O += P V, 2-term fp16 (P split, V hi) ----
        #pragma unroll
        for (int ks = 0; ks < 4; ks++) {
            uint32_t ph[4], pl[4];
            split2h(sf[2 * ks][0],     sf[2 * ks][1],     ph[0], pl[0]);
            split2h(sf[2 * ks][2],     sf[2 * ks][3],     ph[1], pl[1]);
            split2h(sf[2 * ks + 1][0], sf[2 * ks + 1][1], ph[2], pl[2]);
            split2h(sf[2 * ks + 1][2], sf[2 * ks + 1][3], ph[3], pl[3]);
            #pragma unroll
            for (int nb = 0; nb < 8; nb++) {
                uint32_t vh4[4];
                ldsm_x4_t(vh4, st + KTILE + vboff + ks * 16 * ROWB + nb * 32);
                mma_f16(of[2 * nb],     ph, vh4);
                mma_f16(of[2 * nb + 1], ph, vh4 + 2);
                mma_f16(of[2 * nb],     pl, vh4);
                mma_f16(of[2 * nb + 1], pl, vh4 + 2);
            }
        }
        __syncthreads();
    }

    // ---- epilogue ----
    float inv0 = 1.f / l_[0], inv1 = 1.f / l_[1];
    size_t base0 = ((size_t)(b * SEQ + rbase) * NH + h) * HD + ((lane & 3) << 1);
    size_t base1 = base0 + (size_t)8 * NH * HD;
    #pragma unroll
    for (int nf = 0; nf < 16; nf++) {
        *(float2*)(Og + base0 + nf * 8) = make_float2(of[nf][0] * inv0, of[nf][1] * inv0);
        *(float2*)(Og + base1 + nf * 8) = make_float2(of[nf][2] * inv1, of[nf][3] * inv1);
    }
}

// ============================================================================
// host launcher
// ============================================================================
extern "C" void kernel_launch(void* const* d_in, const int* in_sizes, int n_in,
                              void* d_out, int out_size)
{
    const float* x  = (const float*)d_in[0];
    const float* fc = (const float*)d_in[1];
    const float* fs = (const float*)d_in[2];
    const float* wq = (const float*)d_in[4];
    const float* wk = (const float*)d_in[5];
    const float* wv = (const float*)d_in[6];
    const float* wo = (const float*)d_in[7];
    float* out = (float*)d_out;

    float *q, *k, *v, *ao;
    __half *x2, *ao2, *wqh, *wkh, *wvh, *woh, *qh2, *ql2, *kh2, *vh2;
    cudaGetSymbolAddress((void**)&q,   g_q);
    cudaGetSymbolAddress((void**)&k,   g_k);
    cudaGetSymbolAddress((void**)&v,   g_v);
    cudaGetSymbolAddress((void**)&ao,  g_ao);
    cudaGetSymbolAddress((void**)&x2,  g_x2);
    cudaGetSymbolAddress((void**)&ao2, g_ao2);
    cudaGetSymbolAddress((void**)&wqh, g_wqh);
    cudaGetSymbolAddress((void**)&wkh, g_wkh);
    cudaGetSymbolAddress((void**)&wvh, g_wvh);
    cudaGetSymbolAddress((void**)&woh, g_woh);
    cudaGetSymbolAddress((void**)&qh2, g_qh2);
    cudaGetSymbolAddress((void**)&ql2, g_ql2);
    cudaGetSymbolAddress((void**)&kh2, g_kh2);
    cudaGetSymbolAddress((void**)&vh2, g_vh2);

    cudaFuncSetAttribute(bgemm16, cudaFuncAttributeMaxDynamicSharedMemorySize,
                         GEMM16_SMEM);
    cudaFuncSetAttribute(attn_mma, cudaFuncAttributeMaxDynamicSharedMemorySize,
                         ATT_SMEM);

    // ---- conversions ----
    {
        size_t t4;
        t4 = (size_t)MROWS * DMODEL / 4;
        convert_2h<<<(unsigned)((t4 + 255) / 256), 256>>>((const float4*)x, x2, t4);
        t4 = (size_t)QE * DMODEL / 4;
        convert_h<<<(unsigned)((t4 + 255) / 256), 256>>>((const float4*)wq, wqh, t4);
        t4 = (size_t)KVE * DMODEL / 4;
        convert_h<<<(unsigned)((t4 + 255) / 256), 256>>>((const float4*)wk, wkh, t4);
        convert_h<<<(unsigned)((t4 + 255) / 256), 256>>>((const float4*)wv, wvh, t4);
        t4 = (size_t)DMODEL * DMODEL / 4;
        convert_h<<<(unsigned)((t4 + 255) / 256), 256>>>((const float4*)wo, woh, t4);
    }

    // ---- Q projection (512 CTAs), K+V merged (256 CTAs) ----
    bgemm16<<<dim3(QE / 128, MROWS / 128), 256, GEMM16_SMEM>>>(
        x2, wqh, wqh, q, q, QE, QE, QE / 128);
    bgemm16<<<dim3(2 * KVE / 128, MROWS / 128), 256, GEMM16_SMEM>>>(
        x2, wkh, wvh, k, v, KVE, KVE, KVE / 128);

    // ---- RoPE + fp16 splits ----
    {
        int tp_q = MROWS * NH  * (HD / 2);
        int tp_k = MROWS * NKV * (HD / 2);
        rope_split_h<<<(tp_q + 255) / 256, 256>>>(q, fc, fs, qh2, ql2, NH,  tp_q);
        rope_split_h<<<(tp_k + 255) / 256, 256>>>(k, fc, fs, kh2, (__half*)nullptr,
                                                  NKV, tp_k);
        size_t t4 = (size_t)MROWS * KVE / 4;
        convert_h<<<(unsigned)((t4 + 255) / 256), 256>>>((const float4*)v, vh2, t4);
    }

    // ---- tensor-core causal attention ----
    attn_mma<<<dim3(SEQ / 128, NH, BB), 256, ATT_SMEM>>>(qh2, ql2, kh2, vh2, ao);

    // ---- output projection ----
    {
        size_t t4 = (size_t)MROWS * DMODEL / 4;
        convert_2h<<<(unsigned)((t4 + 255) / 256), 256>>>((const float4*)ao, ao2, t4);
    }
    bgemm16<<<dim3(DMODEL / 128, MROWS / 128), 256, GEMM16_SMEM>>>(
        ao2, woh, woh, out, out, DMODEL, DMODEL, DMODEL / 128);
}

// round 7
// speedup vs baseline: 6.6124x; 1.0284x over previous
#include <cuda_runtime.h>
#include <cuda_fp16.h>
#include <math.h>
#include <cstdint>

// ---------------- problem constants ----------------
constexpr int BB     = 2;
constexpr int SEQ    = 2048;
constexpr int DMODEL = 2048;
constexpr int NH     = 16;
constexpr int NKV    = 4;
constexpr int HD     = 128;
constexpr int MROWS  = BB * SEQ;     // 4096
constexpr int QE     = NH * HD;      // 2048
constexpr int KVE    = NKV * HD;     // 512
constexpr int K2     = 4096;         // 2-term fp16 split K
constexpr int NCH2   = 128;          // chunks of 32

// ---------------- scratch ----------------
__device__ __half g_x2 [(size_t)MROWS * K2];    // [xh | xl]
__device__ __half g_ao2[(size_t)MROWS * K2];    // [aoh | aol]
__device__ __half g_wqh[(size_t)QE     * DMODEL];
__device__ __half g_wkh[(size_t)KVE    * DMODEL];
__device__ __half g_wvh[(size_t)KVE    * DMODEL];
__device__ __half g_woh[(size_t)DMODEL * DMODEL];

__device__ __half g_qh2[(size_t)MROWS * QE];
__device__ __half g_ql2[(size_t)MROWS * QE];
__device__ __half g_kh2[(size_t)MROWS * KVE];
__device__ __half g_vh2[(size_t)MROWS * KVE];

// ---------------- helpers ----------------
__device__ __forceinline__ uint32_t smem_u32(const void* p) {
    uint32_t a;
    asm("{ .reg .u64 t; cvta.to.shared.u64 t, %1; cvt.u32.u64 %0, t; }"
        : "=r"(a) : "l"(p));
    return a;
}
__device__ __forceinline__ void cp16(uint32_t dst, const void* src) {
    asm volatile("cp.async.cg.shared.global [%0], [%1], 16;"
                 :: "r"(dst), "l"(src));
}
__device__ __forceinline__ void ldsm_x4(uint32_t* r, uint32_t addr) {
    asm volatile("ldmatrix.sync.aligned.m8n8.x4.shared.b16 {%0,%1,%2,%3}, [%4];"
                 : "=r"(r[0]), "=r"(r[1]), "=r"(r[2]), "=r"(r[3]) : "r"(addr));
}
__device__ __forceinline__ void ldsm_x4_t(uint32_t* r, uint32_t addr) {
    asm volatile("ldmatrix.sync.aligned.m8n8.x4.trans.shared.b16 {%0,%1,%2,%3}, [%4];"
                 : "=r"(r[0]), "=r"(r[1]), "=r"(r[2]), "=r"(r[3]) : "r"(addr));
}
__device__ __forceinline__ void mma_f16(float* d, const uint32_t* a,
                                        const uint32_t* b) {
    asm volatile(
        "mma.sync.aligned.m16n8k16.row.col.f32.f16.f16.f32 "
        "{%0,%1,%2,%3}, {%4,%5,%6,%7}, {%8,%9}, {%0,%1,%2,%3};"
        : "+f"(d[0]), "+f"(d[1]), "+f"(d[2]), "+f"(d[3])
        : "r"(a[0]), "r"(a[1]), "r"(a[2]), "r"(a[3]), "r"(b[0]), "r"(b[1]));
}
__device__ __forceinline__ uint32_t pack_f16(float lo, float hi) {
    uint32_t r;
    asm("cvt.rn.f16x2.f32 %0, %1, %2;" : "=r"(r) : "f"(hi), "f"(lo));
    return r;
}
__device__ __forceinline__ void split2h(float x, float y, uint32_t& hi, uint32_t& lo) {
    uint32_t h = pack_f16(x, y);
    __half2 hb = *reinterpret_cast<__half2*>(&h);
    lo = pack_f16(x - __half2float(hb.x), y - __half2float(hb.y));
    hi = h;
}

// ============================================================================
// converts
// ============================================================================
__global__ __launch_bounds__(256)
void convert_2h(const float4* __restrict__ src, __half* __restrict__ dst,
                size_t total4)
{
    size_t i = (size_t)blockIdx.x * blockDim.x + threadIdx.x;
    if (i >= total4) return;
    float4 v = src[i];
    size_t e = i * 4;
    size_t r = e >> 11;
    int    c = (int)(e & 2047);
    float xs[4] = {v.x, v.y, v.z, v.w};
    __half* d = dst + r * (size_t)K2 + c;
    #pragma unroll
    for (int j = 0; j < 4; j++) {
        __half h = __float2half(xs[j]);
        d[j]          = h;
        d[DMODEL + j] = __float2half(xs[j] - __half2float(h));
    }
}
__global__ __launch_bounds__(256)
void convert_h(const float4* __restrict__ src, __half* __restrict__ dst,
               size_t total4)
{
    size_t i = (size_t)blockIdx.x * blockDim.x + threadIdx.x;
    if (i >= total4) return;
    float4 v = src[i];
    size_t e = i * 4;
    dst[e]     = __float2half(v.x);
    dst[e + 1] = __float2half(v.y);
    dst[e + 2] = __float2half(v.z);
    dst[e + 3] = __float2half(v.w);
}

// ============================================================================
// shared GEMM config
// ============================================================================
constexpr int HROWB  = 80;                 // bytes per smem row (40 halves)
constexpr int GTILE  = 128 * HROWB;        // 10240 B
constexpr int GSTAGE = 2 * GTILE;
constexpr int GEMM16_SMEM = 4 * GSTAGE;    // 81920

// shared mainloop: computes acc for (m0, Bbase), A is [Ah|Al] at stride K2
template <typename EPI>
__device__ __forceinline__
void gemm16_body(const __half* __restrict__ A, const __half* __restrict__ Bw,
                 int m0, int n0loc, EPI epi)
{
    extern __shared__ char sm[];
    const uint32_t sb = smem_u32(sm);
    const int tid = threadIdx.x;
    const int wid = tid >> 5;
    const int lane = tid & 31;
    const int wm = (wid >> 2) * 64;
    const int wn = (wid & 3) * 32;

    const __half* Abase = A  + (size_t)m0 * K2;
    const __half* Bbase = Bw + (size_t)n0loc * DMODEL;

    const int grp = lane >> 3, lr = lane & 7;
    uint32_t aoff[4], boff[2];
    #pragma unroll
    for (int mf = 0; mf < 4; mf++)
        aoff[mf] = (wm + mf * 16 + (grp & 1) * 8 + lr) * HROWB + (grp >> 1) * 16;
    #pragma unroll
    for (int nf2 = 0; nf2 < 2; nf2++)
        boff[nf2] = GTILE + (wn + nf2 * 16 + (grp >> 1) * 8 + lr) * HROWB
                  + (grp & 1) * 16;

    float acc[4][4][4];
    #pragma unroll
    for (int mf = 0; mf < 4; mf++)
        #pragma unroll
        for (int nf = 0; nf < 4; nf++)
            #pragma unroll
            for (int e = 0; e < 4; e++) acc[mf][nf][e] = 0.f;

    auto issue = [&](int c) {
        if (c >= NCH2) return;
        const uint32_t st = sb + (c & 3) * GSTAGE;
        const __half* Ag = Abase + c * 32;
        const __half* Bg = Bbase + (c & 63) * 32;
        #pragma unroll
        for (int t = 0; t < 2; t++) {
            int i = tid + t * 256;
            int row = i >> 2, seg = i & 3;
            cp16(st + row * HROWB + seg * 16, Ag + (size_t)row * K2 + seg * 8);
        }
        #pragma unroll
        for (int t = 0; t < 2; t++) {
            int i = tid + t * 256;
            int row = i >> 2, seg = i & 3;
            cp16(st + GTILE + row * HROWB + seg * 16,
                 Bg + (size_t)row * DMODEL + seg * 8);
        }
    };

    issue(0); asm volatile("cp.async.commit_group;" ::: "memory");
    issue(1); asm volatile("cp.async.commit_group;" ::: "memory");
    issue(2); asm volatile("cp.async.commit_group;" ::: "memory");

    for (int c = 0; c < NCH2; c++) {
        asm volatile("cp.async.wait_group 2;" ::: "memory");
        __syncthreads();
        issue(c + 3);
        asm volatile("cp.async.commit_group;" ::: "memory");

        const uint32_t st = sb + (c & 3) * GSTAGE;
        #pragma unroll
        for (int s = 0; s < 2; s++) {
            const uint32_t koff = s * 32;
            uint32_t ar[4][4], br[2][4];
            #pragma unroll
            for (int mf = 0; mf < 4; mf++) ldsm_x4(ar[mf], st + aoff[mf] + koff);
            #pragma unroll
            for (int nf2 = 0; nf2 < 2; nf2++) ldsm_x4(br[nf2], st + boff[nf2] + koff);
            #pragma unroll
            for (int mf = 0; mf < 4; mf++)
                #pragma unroll
                for (int nf = 0; nf < 4; nf++)
                    mma_f16(acc[mf][nf], ar[mf], &br[nf >> 1][(nf & 1) * 2]);
        }
    }

    const int lr4 = lane >> 2, lc2 = (lane & 3) * 2;
    #pragma unroll
    for (int mf = 0; mf < 4; mf++) {
        int r = m0 + wm + mf * 16 + lr4;
        #pragma unroll
        for (int nf = 0; nf < 4; nf++) {
            int cc = wn + nf * 8 + lc2;     // local n within tile
            epi(r,     cc, acc[mf][nf][0], acc[mf][nf][1]);
            epi(r + 8, cc, acc[mf][nf][2], acc[mf][nf][3]);
        }
    }
}

// ============================================================================
// fused QKV projection: one launch, epilogue does RoPE + fp16 split
// grid: x = 16(Q) + 4(K) + 4(V), y = 32
// ============================================================================
__global__ __launch_bounds__(256, 2)
void qkv_gemm(const __half* __restrict__ x2,
              const __half* __restrict__ wqh, const __half* __restrict__ wkh,
              const __half* __restrict__ wvh,
              const float* __restrict__ fc, const float* __restrict__ fs,
              __half* __restrict__ qh2, __half* __restrict__ ql2,
              __half* __restrict__ kh2, __half* __restrict__ vh2)
{
    const int bx = blockIdx.x;
    const int m0 = blockIdx.y * 128;

    if (bx < 16) {             // ---- Q: rope + hi/lo split ----
        const int n0 = bx * 128;
        gemm16_body(x2, wqh, m0, n0,
            [&](int r, int cc, float e, float o) {
                int col = n0 + cc;
                int s = r & (SEQ - 1);
                int p = (col & 127) >> 1;
                float c  = fc[s * 64 + p];
                float si = fs[s * 64 + p];
                float re = e * c - o * si;
                float ro = e * si + o * c;
                uint32_t hi, lo;
                split2h(re, ro, hi, lo);
                size_t idx = (size_t)r * QE + col;
                *(uint32_t*)(qh2 + idx) = hi;
                *(uint32_t*)(ql2 + idx) = lo;
            });
    } else if (bx < 20) {      // ---- K: rope, hi only ----
        const int n0 = (bx - 16) * 128;
        gemm16_body(x2, wkh, m0, n0,
            [&](int r, int cc, float e, float o) {
                int col = n0 + cc;
                int s = r & (SEQ - 1);
                int p = (col & 127) >> 1;
                float c  = fc[s * 64 + p];
                float si = fs[s * 64 + p];
                float re = e * c - o * si;
                float ro = e * si + o * c;
                *(uint32_t*)(kh2 + (size_t)r * KVE + col) = pack_f16(re, ro);
            });
    } else {                   // ---- V: hi only ----
        const int n0 = (bx - 20) * 128;
        gemm16_body(x2, wvh, m0, n0,
            [&](int r, int cc, float e, float o) {
                *(uint32_t*)(vh2 + (size_t)r * KVE + n0 + cc) = pack_f16(e, o);
            });
    }
}

// ============================================================================
// output projection: plain fp32 store
// ============================================================================
__global__ __launch_bounds__(256, 2)
void wo_gemm(const __half* __restrict__ ao2, const __half* __restrict__ woh,
             float* __restrict__ out)
{
    const int n0 = blockIdx.x * 128;
    const int m0 = blockIdx.y * 128;
    gemm16_body(ao2, woh, m0, n0,
        [&](int r, int cc, float e, float o) {
            *(float2*)(out + (size_t)r * DMODEL + n0 + cc) = make_float2(e, o);
        });
}

// ============================================================================
// fp16 2-term tensor-core causal flash attention (Br=128, Bc=64)
// epilogue writes [hi|lo] fp16 directly into ao2
// ============================================================================
constexpr int ATT_STRIDE = 136;
constexpr int ROWB  = ATT_STRIDE * 2;        // 272 B
constexpr int QTILE = 128 * ROWB;            // 34816
constexpr int KTILE = 64 * ROWB;             // 17408
constexpr int ATT_SMEM = 2 * QTILE + 2 * 2 * KTILE;  // 139264

__global__ __launch_bounds__(256)
void attn_mma(const __half* __restrict__ Qh, const __half* __restrict__ Ql,
              const __half* __restrict__ Kh, const __half* __restrict__ Vh,
              __half* __restrict__ ao2)
{
    extern __shared__ char sm[];
    const uint32_t sb = smem_u32(sm);

    const int qb = gridDim.x - 1 - blockIdx.x;
    const int h  = blockIdx.y;
    const int b  = blockIdx.z;
    const int kh = h >> 2;
    const int tid = threadIdx.x;
    const int wid = tid >> 5;
    const int lane = tid & 31;
    const int q0 = qb * 128;
    const int nkb = q0 / 64 + 2;

    {
        const size_t qrow = ((size_t)(b * SEQ + q0) * NH + h) * HD;
        for (int i = tid; i < 2048; i += 256) {
            int r = i >> 4, ch = i & 15;
            size_t g = qrow + (size_t)r * NH * HD + ch * 8;
            uint32_t so = r * ROWB + ch * 16;
            cp16(sb + so, Qh + g);
            cp16(sb + QTILE + so, Ql + g);
        }
    }

    auto issue_kv = [&](int kb) {
        const uint32_t st = sb + 2 * QTILE + (kb & 1) * (2 * KTILE);
        const size_t kvrow = ((size_t)(b * SEQ + kb * 64) * NKV + kh) * HD;
        for (int i = tid; i < 1024; i += 256) {
            int r = i >> 4, ch = i & 15;
            size_t g = kvrow + (size_t)r * NKV * HD + ch * 8;
            uint32_t so = r * ROWB + ch * 16;
            cp16(st + so,         Kh + g);
            cp16(st + KTILE + so, Vh + g);
        }
    };

    issue_kv(0);
    asm volatile("cp.async.commit_group;" ::: "memory");

    const int grp = lane >> 3, lr = lane & 7;
    const uint32_t qa_h = sb + (wid * 16 + (grp & 1) * 8 + lr) * ROWB + (grp >> 1) * 16;
    const uint32_t qa_l = qa_h + QTILE;
    const uint32_t kboff = ((grp >> 1) * 8 + lr) * ROWB + (grp & 1) * 16;
    const uint32_t vboff = ((grp & 1) * 8 + lr) * ROWB + (grp >> 1) * 16;

    float m_[2] = {-1e30f, -1e30f};
    float l_[2] = {0.f, 0.f};
    float of[16][4];
    #pragma unroll
    for (int nf = 0; nf < 16; nf++)
        #pragma unroll
        for (int e = 0; e < 4; e++) of[nf][e] = 0.f;

    const float scale = 0.08838834764831845f;
    const int rbase = q0 + wid * 16 + (lane >> 2);

    for (int kb = 0; kb < nkb; kb++) {
        if (kb + 1 < nkb) {
            issue_kv(kb + 1);
            asm volatile("cp.async.commit_group;" ::: "memory");
            asm volatile("cp.async.wait_group 1;" ::: "memory");
        } else {
            asm volatile("cp.async.wait_group 0;" ::: "memory");
        }
        __syncthreads();

        const uint32_t st = sb + 2 * QTILE + (kb & 1) * (2 * KTILE);

        float sf[8][4];
        #pragma unroll
        for (int f = 0; f < 8; f++)
            #pragma unroll
            for (int e = 0; e < 4; e++) sf[f][e] = 0.f;

        #pragma unroll
        for (int ks = 0; ks < 8; ks++) {
            uint32_t ah[4], al[4];
            ldsm_x4(ah, qa_h + ks * 32);
            ldsm_x4(al, qa_l + ks * 32);
            #pragma unroll
            for (int nb = 0; nb < 4; nb++) {
                uint32_t bh[4];
                ldsm_x4(bh, st + kboff + nb * 16 * ROWB + ks * 32);
                mma_f16(sf[2 * nb],     ah, bh);
                mma_f16(sf[2 * nb + 1], ah, bh + 2);
                mma_f16(sf[2 * nb],     al, bh);
                mma_f16(sf[2 * nb + 1], al, bh + 2);
            }
        }

        float mx[2] = {-1e30f, -1e30f};
        #pragma unroll
        for (int f = 0; f < 8; f++)
            #pragma unroll
            for (int e = 0; e < 4; e++) {
                float v = sf[f][e] * scale;
                int col = kb * 64 + f * 8 + ((lane & 3) << 1) + (e & 1);
                int row = rbase + ((e & 2) << 2);
                v = (col > row) ? -1e30f : v;
                sf[f][e] = v;
                mx[e >> 1] = fmaxf(mx[e >> 1], v);
            }
        #pragma unroll
        for (int e = 0; e < 2; e++) {
            mx[e] = fmaxf(mx[e], __shfl_xor_sync(0xffffffffu, mx[e], 1));
            mx[e] = fmaxf(mx[e], __shfl_xor_sync(0xffffffffu, mx[e], 2));
        }
        float mn[2], alp[2], rs[2] = {0.f, 0.f};
        #pragma unroll
        for (int e = 0; e < 2; e++) {
            mn[e]  = fmaxf(m_[e], mx[e]);
            alp[e] = __expf(m_[e] - mn[e]);
            m_[e]  = mn[e];
        }
        #pragma unroll
        for (int f = 0; f < 8; f++)
            #pragma unroll
            for (int e = 0; e < 4; e++) {
                float p = __expf(sf[f][e] - mn[e >> 1]);
                sf[f][e] = p;
                rs[e >> 1] += p;
            }
        #pragma unroll
        for (int e = 0; e < 2; e++) {
            rs[e] += __shfl_xor_sync(0xffffffffu, rs[e], 1);
            rs[e] += __shfl_xor_sync(0xffffffffu, rs[e], 2);
            l_[e] = l_[e] * alp[e] + rs[e];
        }
        #pragma unroll
        for (int nf = 0; nf < 16; nf++) {
            of[nf][0] *= alp[0]; of[nf][1] *= alp[0];
            of[nf][2] *= alp[1]; of[nf][3] *= alp[1];
        }

        #pragma unroll
        for (int ks = 0; ks < 4; ks++) {
            uint32_t ph[4], pl[4];
            split2h(sf[2 * ks][0],     sf[2 * ks][1],     ph[0], pl[0]);
            split2h(sf[2 * ks][2],     sf[2 * ks][3],     ph[1], pl[1]);
            split2h(sf[2 * ks + 1][0], sf[2 * ks + 1][1], ph[2], pl[2]);
            split2h(sf[2 * ks + 1][2], sf[2 * ks + 1][3], ph[3], pl[3]);
            #pragma unroll
            for (int nb = 0; nb < 8; nb++) {
                uint32_t vh4[4];
                ldsm_x4_t(vh4, st + KTILE + vboff + ks * 16 * ROWB + nb * 32);
                mma_f16(of[2 * nb],     ph, vh4);
                mma_f16(of[2 * nb + 1], ph, vh4 + 2);
                mma_f16(of[2 * nb],     pl, vh4);
                mma_f16(of[2 * nb + 1], pl, vh4 + 2);
            }
        }
        __syncthreads();
    }

    // ---- epilogue: normalize + hi/lo split straight into ao2 ----
    float inv0 = 1.f / l_[0], inv1 = 1.f / l_[1];
    size_t b0 = (size_t)(b * SEQ + rbase) * K2 + h * HD + ((lane & 3) << 1);
    size_t b1 = b0 + (size_t)8 * K2;
    #pragma unroll
    for (int nf = 0; nf < 16; nf++) {
        uint32_t hi, lo;
        split2h(of[nf][0] * inv0, of[nf][1] * inv0, hi, lo);
        *(uint32_t*)(ao2 + b0 + nf * 8)          = hi;
        *(uint32_t*)(ao2 + b0 + DMODEL + nf * 8) = lo;
        split2h(of[nf][2] * inv1, of[nf][3] * inv1, hi, lo);
        *(uint32_t*)(ao2 + b1 + nf * 8)          = hi;
        *(uint32_t*)(ao2 + b1 + DMODEL + nf * 8) = lo;
    }
}

// ============================================================================
// host launcher
// ============================================================================
extern "C" void kernel_launch(void* const* d_in, const int* in_sizes, int n_in,
                              void* d_out, int out_size)
{
    const float* x  = (const float*)d_in[0];
    const float* fc = (const float*)d_in[1];
    const float* fs = (const float*)d_in[2];
    const float* wq = (const float*)d_in[4];
    const float* wk = (const float*)d_in[5];
    const float* wv = (const float*)d_in[6];
    const float* wo = (const float*)d_in[7];
    float* out = (float*)d_out;

    __half *x2, *ao2, *wqh, *wkh, *wvh, *woh, *qh2, *ql2, *kh2, *vh2;
    cudaGetSymbolAddress((void**)&x2,  g_x2);
    cudaGetSymbolAddress((void**)&ao2, g_ao2);
    cudaGetSymbolAddress((void**)&wqh, g_wqh);
    cudaGetSymbolAddress((void**)&wkh, g_wkh);
    cudaGetSymbolAddress((void**)&wvh, g_wvh);
    cudaGetSymbolAddress((void**)&woh, g_woh);
    cudaGetSymbolAddress((void**)&qh2, g_qh2);
    cudaGetSymbolAddress((void**)&ql2, g_ql2);
    cudaGetSymbolAddress((void**)&kh2, g_kh2);
    cudaGetSymbolAddress((void**)&vh2, g_vh2);

    cudaFuncSetAttribute(qkv_gemm, cudaFuncAttributeMaxDynamicSharedMemorySize,
                         GEMM16_SMEM);
    cudaFuncSetAttribute(wo_gemm, cudaFuncAttributeMaxDynamicSharedMemorySize,
                         GEMM16_SMEM);
    cudaFuncSetAttribute(attn_mma, cudaFuncAttributeMaxDynamicSharedMemorySize,
                         ATT_SMEM);

    // ---- conversions ----
    {
        size_t t4;
        t4 = (size_t)MROWS * DMODEL / 4;
        convert_2h<<<(unsigned)((t4 + 255) / 256), 256>>>((const float4*)x, x2, t4);
        t4 = (size_t)QE * DMODEL / 4;
        convert_h<<<(unsigned)((t4 + 255) / 256), 256>>>((const float4*)wq, wqh, t4);
        t4 = (size_t)KVE * DMODEL / 4;
        convert_h<<<(unsigned)((t4 + 255) / 256), 256>>>((const float4*)wk, wkh, t4);
        convert_h<<<(unsigned)((t4 + 255) / 256), 256>>>((const float4*)wv, wvh, t4);
        t4 = (size_t)DMODEL * DMODEL / 4;
        convert_h<<<(unsigned)((t4 + 255) / 256), 256>>>((const float4*)wo, woh, t4);
    }

    // ---- fused QKV projection + RoPE + fp16 split (one launch) ----
    qkv_gemm<<<dim3(24, MROWS / 128), 256, GEMM16_SMEM>>>(
        x2, wqh, wkh, wvh, fc, fs, qh2, ql2, kh2, vh2);

    // ---- tensor-core causal attention (writes ao2 hi/lo) ----
    attn_mma<<<dim3(SEQ / 128, NH, BB), 256, ATT_SMEM>>>(qh2, ql2, kh2, vh2, ao2);

    // ---- output projection ----
    wo_gemm<<<dim3(DMODEL / 128, MROWS / 128), 256, GEMM16_SMEM>>>(ao2, woh, out);
}

// round 8
// speedup vs baseline: 6.8173x; 1.0310x over previous
#include <cuda_runtime.h>
#include <cuda_fp16.h>
#include <math.h>
#include <cstdint>

// ---------------- problem constants ----------------
constexpr int BB     = 2;
constexpr int SEQ    = 2048;
constexpr int DMODEL = 2048;
constexpr int NH     = 16;
constexpr int NKV    = 4;
constexpr int HD     = 128;
constexpr int MROWS  = BB * SEQ;     // 4096
constexpr int QE     = NH * HD;      // 2048
constexpr int KVE    = NKV * HD;     // 512
constexpr int K2     = 4096;         // 2-term fp16 split K
constexpr int NCH2   = 128;          // chunks of 32

// ---------------- scratch ----------------
__device__ __half g_x2 [(size_t)MROWS * K2];    // [xh | xl]
__device__ __half g_ao2[(size_t)MROWS * K2];    // [aoh | aol]
__device__ __half g_wqh[(size_t)QE     * DMODEL];
__device__ __half g_wkh[(size_t)KVE    * DMODEL];
__device__ __half g_wvh[(size_t)KVE    * DMODEL];
__device__ __half g_woh[(size_t)DMODEL * DMODEL];

__device__ __half g_qh2[(size_t)MROWS * QE];
__device__ __half g_ql2[(size_t)MROWS * QE];
__device__ __half g_kh2[(size_t)MROWS * KVE];
__device__ __half g_vh2[(size_t)MROWS * KVE];

// ---------------- helpers ----------------
__device__ __forceinline__ uint32_t smem_u32(const void* p) {
    uint32_t a;
    asm("{ .reg .u64 t; cvta.to.shared.u64 t, %1; cvt.u32.u64 %0, t; }"
        : "=r"(a) : "l"(p));
    return a;
}
__device__ __forceinline__ void cp16(uint32_t dst, const void* src) {
    asm volatile("cp.async.cg.shared.global [%0], [%1], 16;"
                 :: "r"(dst), "l"(src));
}
__device__ __forceinline__ void ldsm_x4(uint32_t* r, uint32_t addr) {
    asm volatile("ldmatrix.sync.aligned.m8n8.x4.shared.b16 {%0,%1,%2,%3}, [%4];"
                 : "=r"(r[0]), "=r"(r[1]), "=r"(r[2]), "=r"(r[3]) : "r"(addr));
}
__device__ __forceinline__ void ldsm_x4_t(uint32_t* r, uint32_t addr) {
    asm volatile("ldmatrix.sync.aligned.m8n8.x4.trans.shared.b16 {%0,%1,%2,%3}, [%4];"
                 : "=r"(r[0]), "=r"(r[1]), "=r"(r[2]), "=r"(r[3]) : "r"(addr));
}
__device__ __forceinline__ void mma_f16(float* d, const uint32_t* a,
                                        const uint32_t* b) {
    asm volatile(
        "mma.sync.aligned.m16n8k16.row.col.f32.f16.f16.f32 "
        "{%0,%1,%2,%3}, {%4,%5,%6,%7}, {%8,%9}, {%0,%1,%2,%3};"
        : "+f"(d[0]), "+f"(d[1]), "+f"(d[2]), "+f"(d[3])
        : "r"(a[0]), "r"(a[1]), "r"(a[2]), "r"(a[3]), "r"(b[0]), "r"(b[1]));
}
__device__ __forceinline__ uint32_t pack_f16(float lo, float hi) {
    uint32_t r;
    asm("cvt.rn.f16x2.f32 %0, %1, %2;" : "=r"(r) : "f"(hi), "f"(lo));
    return r;
}
__device__ __forceinline__ void split2h(float x, float y, uint32_t& hi, uint32_t& lo) {
    uint32_t h = pack_f16(x, y);
    __half2 hb = *reinterpret_cast<__half2*>(&h);
    lo = pack_f16(x - __half2float(hb.x), y - __half2float(hb.y));
    hi = h;
}

// ============================================================================
// merged conversion kernel: x -> [hi|lo], weights -> fp16
// quad ranges: x 2097152 | wq 1048576 | wk 262144 | wv 262144 | wo 1048576
// ============================================================================
constexpr size_t CQ_X  = 2097152;
constexpr size_t CQ_WQ = CQ_X  + 1048576;   // 3145728
constexpr size_t CQ_WK = CQ_WQ + 262144;    // 3407872
constexpr size_t CQ_WV = CQ_WK + 262144;    // 3670016
constexpr size_t CQ_WO = CQ_WV + 1048576;   // 4718592

__global__ __launch_bounds__(256)
void convert_all(const float4* __restrict__ x,  const float4* __restrict__ wq,
                 const float4* __restrict__ wk, const float4* __restrict__ wv,
                 const float4* __restrict__ wo,
                 __half* __restrict__ x2,  __half* __restrict__ wqh,
                 __half* __restrict__ wkh, __half* __restrict__ wvh,
                 __half* __restrict__ woh)
{
    size_t i = (size_t)blockIdx.x * 256 + threadIdx.x;
    if (i < CQ_X) {
        float4 v = x[i];
        size_t e = i * 4;
        size_t r = e >> 11;
        int    c = (int)(e & 2047);
        float xs[4] = {v.x, v.y, v.z, v.w};
        __half* d = x2 + r * (size_t)K2 + c;
        #pragma unroll
        for (int j = 0; j < 4; j++) {
            __half h = __float2half(xs[j]);
            d[j]          = h;
            d[DMODEL + j] = __float2half(xs[j] - __half2float(h));
        }
        return;
    }
    const float4* src; __half* dst; size_t j;
    if      (i < CQ_WQ) { src = wq; dst = wqh; j = i - CQ_X;  }
    else if (i < CQ_WK) { src = wk; dst = wkh; j = i - CQ_WQ; }
    else if (i < CQ_WV) { src = wv; dst = wvh; j = i - CQ_WK; }
    else                { src = wo; dst = woh; j = i - CQ_WV; }
    float4 v = src[j];
    size_t e = j * 4;
    dst[e]     = __float2half(v.x);
    dst[e + 1] = __float2half(v.y);
    dst[e + 2] = __float2half(v.z);
    dst[e + 3] = __float2half(v.w);
}

// ============================================================================
// shared GEMM config
// ============================================================================
constexpr int HROWB  = 80;                 // bytes per smem row (40 halves)
constexpr int GTILE  = 128 * HROWB;        // 10240 B
constexpr int GSTAGE = 2 * GTILE;
constexpr int GEMM16_SMEM = 4 * GSTAGE;    // 81920

template <typename EPI>
__device__ __forceinline__
void gemm16_body(const __half* __restrict__ A, const __half* __restrict__ Bw,
                 int m0, int n0loc, EPI epi)
{
    extern __shared__ char sm[];
    const uint32_t sb = smem_u32(sm);
    const int tid = threadIdx.x;
    const int wid = tid >> 5;
    const int lane = tid & 31;
    const int wm = (wid >> 2) * 64;
    const int wn = (wid & 3) * 32;

    const __half* Abase = A  + (size_t)m0 * K2;
    const __half* Bbase = Bw + (size_t)n0loc * DMODEL;

    const int grp = lane >> 3, lr = lane & 7;
    uint32_t aoff[4], boff[2];
    #pragma unroll
    for (int mf = 0; mf < 4; mf++)
        aoff[mf] = (wm + mf * 16 + (grp & 1) * 8 + lr) * HROWB + (grp >> 1) * 16;
    #pragma unroll
    for (int nf2 = 0; nf2 < 2; nf2++)
        boff[nf2] = GTILE + (wn + nf2 * 16 + (grp >> 1) * 8 + lr) * HROWB
                  + (grp & 1) * 16;

    float acc[4][4][4];
    #pragma unroll
    for (int mf = 0; mf < 4; mf++)
        #pragma unroll
        for (int nf = 0; nf < 4; nf++)
            #pragma unroll
            for (int e = 0; e < 4; e++) acc[mf][nf][e] = 0.f;

    auto issue = [&](int c) {
        if (c >= NCH2) return;
        const uint32_t st = sb + (c & 3) * GSTAGE;
        const __half* Ag = Abase + c * 32;
        const __half* Bg = Bbase + (c & 63) * 32;
        #pragma unroll
        for (int t = 0; t < 2; t++) {
            int i = tid + t * 256;
            int row = i >> 2, seg = i & 3;
            cp16(st + row * HROWB + seg * 16, Ag + (size_t)row * K2 + seg * 8);
        }
        #pragma unroll
        for (int t = 0; t < 2; t++) {
            int i = tid + t * 256;
            int row = i >> 2, seg = i & 3;
            cp16(st + GTILE + row * HROWB + seg * 16,
                 Bg + (size_t)row * DMODEL + seg * 8);
        }
    };

    issue(0); asm volatile("cp.async.commit_group;" ::: "memory");
    issue(1); asm volatile("cp.async.commit_group;" ::: "memory");
    issue(2); asm volatile("cp.async.commit_group;" ::: "memory");

    for (int c = 0; c < NCH2; c++) {
        asm volatile("cp.async.wait_group 2;" ::: "memory");
        __syncthreads();
        issue(c + 3);
        asm volatile("cp.async.commit_group;" ::: "memory");

        const uint32_t st = sb + (c & 3) * GSTAGE;
        #pragma unroll
        for (int s = 0; s < 2; s++) {
            const uint32_t koff = s * 32;
            uint32_t ar[4][4], br[2][4];
            #pragma unroll
            for (int mf = 0; mf < 4; mf++) ldsm_x4(ar[mf], st + aoff[mf] + koff);
            #pragma unroll
            for (int nf2 = 0; nf2 < 2; nf2++) ldsm_x4(br[nf2], st + boff[nf2] + koff);
            #pragma unroll
            for (int mf = 0; mf < 4; mf++)
                #pragma unroll
                for (int nf = 0; nf < 4; nf++)
                    mma_f16(acc[mf][nf], ar[mf], &br[nf >> 1][(nf & 1) * 2]);
        }
    }

    const int lr4 = lane >> 2, lc2 = (lane & 3) * 2;
    #pragma unroll
    for (int mf = 0; mf < 4; mf++) {
        int r = m0 + wm + mf * 16 + lr4;
        #pragma unroll
        for (int nf = 0; nf < 4; nf++) {
            int cc = wn + nf * 8 + lc2;
            epi(r,     cc, acc[mf][nf][0], acc[mf][nf][1]);
            epi(r + 8, cc, acc[mf][nf][2], acc[mf][nf][3]);
        }
    }
}

// ============================================================================
// fused QKV projection (epilogue: RoPE + fp16 split)
// ============================================================================
__global__ __launch_bounds__(256, 2)
void qkv_gemm(const __half* __restrict__ x2,
              const __half* __restrict__ wqh, const __half* __restrict__ wkh,
              const __half* __restrict__ wvh,
              const float* __restrict__ fc, const float* __restrict__ fs,
              __half* __restrict__ qh2, __half* __restrict__ ql2,
              __half* __restrict__ kh2, __half* __restrict__ vh2)
{
    const int bx = blockIdx.x;
    const int m0 = blockIdx.y * 128;

    if (bx < 16) {
        const int n0 = bx * 128;
        gemm16_body(x2, wqh, m0, n0,
            [&](int r, int cc, float e, float o) {
                int col = n0 + cc;
                int s = r & (SEQ - 1);
                int p = (col & 127) >> 1;
                float c  = fc[s * 64 + p];
                float si = fs[s * 64 + p];
                float re = e * c - o * si;
                float ro = e * si + o * c;
                uint32_t hi, lo;
                split2h(re, ro, hi, lo);
                size_t idx = (size_t)r * QE + col;
                *(uint32_t*)(qh2 + idx) = hi;
                *(uint32_t*)(ql2 + idx) = lo;
            });
    } else if (bx < 20) {
        const int n0 = (bx - 16) * 128;
        gemm16_body(x2, wkh, m0, n0,
            [&](int r, int cc, float e, float o) {
                int col = n0 + cc;
                int s = r & (SEQ - 1);
                int p = (col & 127) >> 1;
                float c  = fc[s * 64 + p];
                float si = fs[s * 64 + p];
                float re = e * c - o * si;
                float ro = e * si + o * c;
                *(uint32_t*)(kh2 + (size_t)r * KVE + col) = pack_f16(re, ro);
            });
    } else {
        const int n0 = (bx - 20) * 128;
        gemm16_body(x2, wvh, m0, n0,
            [&](int r, int cc, float e, float o) {
                *(uint32_t*)(vh2 + (size_t)r * KVE + n0 + cc) = pack_f16(e, o);
            });
    }
}

// ============================================================================
// output projection
// ============================================================================
__global__ __launch_bounds__(256, 2)
void wo_gemm(const __half* __restrict__ ao2, const __half* __restrict__ woh,
             float* __restrict__ out)
{
    const int n0 = blockIdx.x * 128;
    const int m0 = blockIdx.y * 128;
    gemm16_body(ao2, woh, m0, n0,
        [&](int r, int cc, float e, float o) {
            *(float2*)(out + (size_t)r * DMODEL + n0 + cc) = make_float2(e, o);
        });
}

// ============================================================================
// fp16 2-term tensor-core causal flash attention (Br=128, Bc=64)
// Q fragments hoisted to registers; 4-stage KV pipeline in reused smem;
// one barrier per kb iteration.
// ============================================================================
constexpr int ATT_STRIDE = 136;
constexpr int ROWB  = ATT_STRIDE * 2;        // 272 B
constexpr int QTILE = 128 * ROWB;            // 34816 (Q hi or lo tile)
constexpr int KTILE = 64 * ROWB;             // 17408
constexpr int KVSTAGE = 2 * KTILE;           // 34816 (K + V per stage)
constexpr int ATT_SMEM = 4 * KVSTAGE;        // 139264 (Q loads reuse stages 0-1)

__global__ __launch_bounds__(256)
void attn_mma(const __half* __restrict__ Qh, const __half* __restrict__ Ql,
              const __half* __restrict__ Kh, const __half* __restrict__ Vh,
              __half* __restrict__ ao2)
{
    extern __shared__ char sm[];
    const uint32_t sb = smem_u32(sm);

    const int qb = gridDim.x - 1 - blockIdx.x;
    const int h  = blockIdx.y;
    const int b  = blockIdx.z;
    const int kh = h >> 2;
    const int tid = threadIdx.x;
    const int wid = tid >> 5;
    const int lane = tid & 31;
    const int q0 = qb * 128;
    const int nkb = q0 / 64 + 2;

    const int grp = lane >> 3, lr = lane & 7;

    // ---- load Q (hi+lo) into smem stages 0-1, hoist fragments to registers
    {
        const size_t qrow = ((size_t)(b * SEQ + q0) * NH + h) * HD;
        for (int i = tid; i < 2048; i += 256) {
            int r = i >> 4, ch = i & 15;
            size_t g = qrow + (size_t)r * NH * HD + ch * 8;
            uint32_t so = r * ROWB + ch * 16;
            cp16(sb + so, Qh + g);
            cp16(sb + QTILE + so, Ql + g);
        }
    }
    asm volatile("cp.async.commit_group;" ::: "memory");
    asm volatile("cp.async.wait_group 0;" ::: "memory");
    __syncthreads();

    uint32_t qh_r[8][4], ql_r[8][4];
    {
        const uint32_t qa_h = sb + (wid * 16 + (grp & 1) * 8 + lr) * ROWB
                            + (grp >> 1) * 16;
        const uint32_t qa_l = qa_h + QTILE;
        #pragma unroll
        for (int ks = 0; ks < 8; ks++) {
            ldsm_x4(qh_r[ks], qa_h + ks * 32);
            ldsm_x4(ql_r[ks], qa_l + ks * 32);
        }
    }
    __syncthreads();   // all warps done reading Q before KV overwrites smem

    auto issue_kv = [&](int kb) {
        const uint32_t st = sb + (kb & 3) * KVSTAGE;
        const size_t kvrow = ((size_t)(b * SEQ + kb * 64) * NKV + kh) * HD;
        for (int i = tid; i < 1024; i += 256) {
            int r = i >> 4, ch = i & 15;
            size_t g = kvrow + (size_t)r * NKV * HD + ch * 8;
            uint32_t so = r * ROWB + ch * 16;
            cp16(st + so,         Kh + g);
            cp16(st + KTILE + so, Vh + g);
        }
    };

    #pragma unroll
    for (int p = 0; p < 3; p++) {
        if (p < nkb) issue_kv(p);
        asm volatile("cp.async.commit_group;" ::: "memory");
    }

    const uint32_t kboff = ((grp >> 1) * 8 + lr) * ROWB + (grp & 1) * 16;
    const uint32_t vboff = ((grp & 1) * 8 + lr) * ROWB + (grp >> 1) * 16;

    float m_[2] = {-1e30f, -1e30f};
    float l_[2] = {0.f, 0.f};
    float of[16][4];
    #pragma unroll
    for (int nf = 0; nf < 16; nf++)
        #pragma unroll
        for (int e = 0; e < 4; e++) of[nf][e] = 0.f;

    const float scale = 0.08838834764831845f;
    const int rbase = q0 + wid * 16 + (lane >> 2);

    for (int kb = 0; kb < nkb; kb++) {
        asm volatile("cp.async.wait_group 2;" ::: "memory");
        __syncthreads();   // stage kb ready; all warps done with stage kb-1
        if (kb + 3 < nkb) issue_kv(kb + 3);
        asm volatile("cp.async.commit_group;" ::: "memory");

        const uint32_t st = sb + (kb & 3) * KVSTAGE;

        // ---- S = Q K^T (Q frags in registers) ----
        float sf[8][4];
        #pragma unroll
        for (int f = 0; f < 8; f++)
            #pragma unroll
            for (int e = 0; e < 4; e++) sf[f][e] = 0.f;

        #pragma unroll
        for (int ks = 0; ks < 8; ks++) {
            #pragma unroll
            for (int nb = 0; nb < 4; nb++) {
                uint32_t bh[4];
                ldsm_x4(bh, st + kboff + nb * 16 * ROWB + ks * 32);
                mma_f16(sf[2 * nb],     qh_r[ks], bh);
                mma_f16(sf[2 * nb + 1], qh_r[ks], bh + 2);
                mma_f16(sf[2 * nb],     ql_r[ks], bh);
                mma_f16(sf[2 * nb + 1], ql_r[ks], bh + 2);
            }
        }

        // ---- scale + mask + online softmax ----
        float mx[2] = {-1e30f, -1e30f};
        #pragma unroll
        for (int f = 0; f < 8; f++)
            #pragma unroll
            for (int e = 0; e < 4; e++) {
                float v = sf[f][e] * scale;
                int col = kb * 64 + f * 8 + ((lane & 3) << 1) + (e & 1);
                int row = rbase + ((e & 2) << 2);
                v = (col > row) ? -1e30f : v;
                sf[f][e] = v;
                mx[e >> 1] = fmaxf(mx[e >> 1], v);
            }
        #pragma unroll
        for (int e = 0; e < 2; e++) {
            mx[e] = fmaxf(mx[e], __shfl_xor_sync(0xffffffffu, mx[e], 1));
            mx[e] = fmaxf(mx[e], __shfl_xor_sync(0xffffffffu, mx[e], 2));
        }
        float mn[2], alp[2], rs[2] = {0.f, 0.f};
        #pragma unroll
        for (int e = 0; e < 2; e++) {
            mn[e]  = fmaxf(m_[e], mx[e]);
            alp[e] = __expf(m_[e] - mn[e]);
            m_[e]  = mn[e];
        }
        #pragma unroll
        for (int f = 0; f < 8; f++)
            #pragma unroll
            for (int e = 0; e < 4; e++) {
                float p = __expf(sf[f][e] - mn[e >> 1]);
                sf[f][e] = p;
                rs[e >> 1] += p;
            }
        #pragma unroll
        for (int e = 0; e < 2; e++) {
            rs[e] += __shfl_xor_sync(0xffffffffu, rs[e], 1);
            rs[e] += __shfl_xor_sync(0xffffffffu, rs[e], 2);
            l_[e] = l_[e] * alp[e] + rs[e];
        }
        #pragma unroll
        for (int nf = 0; nf < 16; nf++) {
            of[nf][0] *= alp[0]; of[nf][1] *= alp[0];
            of[nf][2] *= alp[1]; of[nf][3] *= alp[1];
        }

        // ---- O += P V ----
        #pragma unroll
        for (int ks = 0; ks < 4; ks++) {
            uint32_t ph[4], pl[4];
            split2h(sf[2 * ks][0],     sf[2 * ks][1],     ph[0], pl[0]);
            split2h(sf[2 * ks][2],     sf[2 * ks][3],     ph[1], pl[1]);
            split2h(sf[2 * ks + 1][0], sf[2 * ks + 1][1], ph[2], pl[2]);
            split2h(sf[2 * ks + 1][2], sf[2 * ks + 1][3], ph[3], pl[3]);
            #pragma unroll
            for (int nb = 0; nb < 8; nb++) {
                uint32_t vh4[4];
                ldsm_x4_t(vh4, st + KTILE + vboff + ks * 16 * ROWB + nb * 32);
                mma_f16(of[2 * nb],     ph, vh4);
                mma_f16(of[2 * nb + 1], ph, vh4 + 2);
                mma_f16(of[2 * nb],     pl, vh4);
                mma_f16(of[2 * nb + 1], pl, vh4 + 2);
            }
        }
        // no trailing barrier: next write target is stage kb-1 (mod 4),
        // which every warp finished before this iteration's top barrier
    }

    // ---- epilogue: normalize + hi/lo split into ao2 ----
    float inv0 = 1.f / l_[0], inv1 = 1.f / l_[1];
    size_t b0 = (size_t)(b * SEQ + rbase) * K2 + h * HD + ((lane & 3) << 1);
    size_t b1 = b0 + (size_t)8 * K2;
    #pragma unroll
    for (int nf = 0; nf < 16; nf++) {
        uint32_t hi, lo;
        split2h(of[nf][0] * inv0, of[nf][1] * inv0, hi, lo);
        *(uint32_t*)(ao2 + b0 + nf * 8)          = hi;
        *(uint32_t*)(ao2 + b0 + DMODEL + nf * 8) = lo;
        split2h(of[nf][2] * inv1, of[nf][3] * inv1, hi, lo);
        *(uint32_t*)(ao2 + b1 + nf * 8)          = hi;
        *(uint32_t*)(ao2 + b1 + DMODEL + nf * 8) = lo;
    }
}

// ============================================================================
// host launcher
// ============================================================================
extern "C" void kernel_launch(void* const* d_in, const int* in_sizes, int n_in,
                              void* d_out, int out_size)
{
    const float* x  = (const float*)d_in[0];
    const float* fc = (const float*)d_in[1];
    const float* fs = (const float*)d_in[2];
    const float* wq = (const float*)d_in[4];
    const float* wk = (const float*)d_in[5];
    const float* wv = (const float*)d_in[6];
    const float* wo = (const float*)d_in[7];
    float* out = (float*)d_out;

    __half *x2, *ao2, *wqh, *wkh, *wvh, *woh, *qh2, *ql2, *kh2, *vh2;
    cudaGetSymbolAddress((void**)&x2,  g_x2);
    cudaGetSymbolAddress((void**)&ao2, g_ao2);
    cudaGetSymbolAddress((void**)&wqh, g_wqh);
    cudaGetSymbolAddress((void**)&wkh, g_wkh);
    cudaGetSymbolAddress((void**)&wvh, g_wvh);
    cudaGetSymbolAddress((void**)&woh, g_woh);
    cudaGetSymbolAddress((void**)&qh2, g_qh2);
    cudaGetSymbolAddress((void**)&ql2, g_ql2);
    cudaGetSymbolAddress((void**)&kh2, g_kh2);
    cudaGetSymbolAddress((void**)&vh2, g_vh2);

    cudaFuncSetAttribute(qkv_gemm, cudaFuncAttributeMaxDynamicSharedMemorySize,
                         GEMM16_SMEM);
    cudaFuncSetAttribute(wo_gemm, cudaFuncAttributeMaxDynamicSharedMemorySize,
                         GEMM16_SMEM);
    cudaFuncSetAttribute(attn_mma, cudaFuncAttributeMaxDynamicSharedMemorySize,
                         ATT_SMEM);

    // ---- single merged conversion launch ----
    convert_all<<<(unsigned)(CQ_WO / 256), 256>>>(
        (const float4*)x, (const float4*)wq, (const float4*)wk,
        (const float4*)wv, (const float4*)wo, x2, wqh, wkh, wvh, woh);

    // ---- fused QKV projection + RoPE + fp16 split ----
    qkv_gemm<<<dim3(24, MROWS / 128), 256, GEMM16_SMEM>>>(
        x2, wqh, wkh, wvh, fc, fs, qh2, ql2, kh2, vh2);

    // ---- tensor-core causal attention ----
    attn_mma<<<dim3(SEQ / 128, NH, BB), 256, ATT_SMEM>>>(qh2, ql2, kh2, vh2, ao2);

    // ---- output projection ----
    wo_gemm<<<dim3(DMODEL / 128, MROWS / 128), 256, GEMM16_SMEM>>>(ao2, woh, out);
}

// round 10
// speedup vs baseline: 6.8481x; 1.0045x over previous
#include <cuda_runtime.h>
#include <cuda_fp16.h>
#include <math.h>
#include <cstdint>

// ---------------- problem constants ----------------
constexpr int BB     = 2;
constexpr int SEQ    = 2048;
constexpr int DMODEL = 2048;
constexpr int NH     = 16;
constexpr int NKV    = 4;
constexpr int HD     = 128;
constexpr int MROWS  = BB * SEQ;     // 4096
constexpr int QE     = NH * HD;      // 2048
constexpr int KVE    = NKV * HD;     // 512
constexpr int K2     = 4096;         // 2-term fp16 split K
constexpr int NCH2   = 128;          // chunks of 32

// ---------------- scratch ----------------
__device__ __half g_x2 [(size_t)MROWS * K2];    // [xh | xl]
__device__ __half g_ao2[(size_t)MROWS * K2];    // [aoh | aol]
__device__ __half g_wqh[(size_t)QE     * DMODEL];
__device__ __half g_wkh[(size_t)KVE    * DMODEL];
__device__ __half g_wvh[(size_t)KVE    * DMODEL];
__device__ __half g_woh[(size_t)DMODEL * DMODEL];

__device__ __half g_qh2[(size_t)MROWS * QE];
__device__ __half g_ql2[(size_t)MROWS * QE];
__device__ __half g_kh2[(size_t)MROWS * KVE];
__device__ __half g_vh2[(size_t)MROWS * KVE];

// ---------------- helpers ----------------
__device__ __forceinline__ uint32_t smem_u32(const void* p) {
    uint32_t a;
    asm("{ .reg .u64 t; cvta.to.shared.u64 t, %1; cvt.u32.u64 %0, t; }"
        : "=r"(a) : "l"(p));
    return a;
}
__device__ __forceinline__ void cp16(uint32_t dst, const void* src) {
    asm volatile("cp.async.cg.shared.global [%0], [%1], 16;"
                 :: "r"(dst), "l"(src));
}
__device__ __forceinline__ void ldsm_x4(uint32_t* r, uint32_t addr) {
    asm volatile("ldmatrix.sync.aligned.m8n8.x4.shared.b16 {%0,%1,%2,%3}, [%4];"
                 : "=r"(r[0]), "=r"(r[1]), "=r"(r[2]), "=r"(r[3]) : "r"(addr));
}
__device__ __forceinline__ void ldsm_x4_t(uint32_t* r, uint32_t addr) {
    asm volatile("ldmatrix.sync.aligned.m8n8.x4.trans.shared.b16 {%0,%1,%2,%3}, [%4];"
                 : "=r"(r[0]), "=r"(r[1]), "=r"(r[2]), "=r"(r[3]) : "r"(addr));
}
__device__ __forceinline__ void mma_f16(float* d, const uint32_t* a,
                                        const uint32_t* b) {
    asm volatile(
        "mma.sync.aligned.m16n8k16.row.col.f32.f16.f16.f32 "
        "{%0,%1,%2,%3}, {%4,%5,%6,%7}, {%8,%9}, {%0,%1,%2,%3};"
        : "+f"(d[0]), "+f"(d[1]), "+f"(d[2]), "+f"(d[3])
        : "r"(a[0]), "r"(a[1]), "r"(a[2]), "r"(a[3]), "r"(b[0]), "r"(b[1]));
}
__device__ __forceinline__ uint32_t pack_f16(float lo, float hi) {
    uint32_t r;
    asm("cvt.rn.f16x2.f32 %0, %1, %2;" : "=r"(r) : "f"(hi), "f"(lo));
    return r;
}
__device__ __forceinline__ void split2h(float x, float y, uint32_t& hi, uint32_t& lo) {
    uint32_t h = pack_f16(x, y);
    __half2 hb = *reinterpret_cast<__half2*>(&h);
    lo = pack_f16(x - __half2float(hb.x), y - __half2float(hb.y));
    hi = h;
}

// ============================================================================
// merged conversion kernel
// ============================================================================
constexpr size_t CQ_X  = 2097152;
constexpr size_t CQ_WQ = CQ_X  + 1048576;
constexpr size_t CQ_WK = CQ_WQ + 262144;
constexpr size_t CQ_WV = CQ_WK + 262144;
constexpr size_t CQ_WO = CQ_WV + 1048576;

__global__ __launch_bounds__(256)
void convert_all(const float4* __restrict__ x,  const float4* __restrict__ wq,
                 const float4* __restrict__ wk, const float4* __restrict__ wv,
                 const float4* __restrict__ wo,
                 __half* __restrict__ x2,  __half* __restrict__ wqh,
                 __half* __restrict__ wkh, __half* __restrict__ wvh,
                 __half* __restrict__ woh)
{
    size_t i = (size_t)blockIdx.x * 256 + threadIdx.x;
    if (i < CQ_X) {
        float4 v = x[i];
        size_t e = i * 4;
        size_t r = e >> 11;
        int    c = (int)(e & 2047);
        float xs[4] = {v.x, v.y, v.z, v.w};
        __half* d = x2 + r * (size_t)K2 + c;
        #pragma unroll
        for (int j = 0; j < 4; j++) {
            __half h = __float2half(xs[j]);
            d[j]          = h;
            d[DMODEL + j] = __float2half(xs[j] - __half2float(h));
        }
        return;
    }
    const float4* src; __half* dst; size_t j;
    if      (i < CQ_WQ) { src = wq; dst = wqh; j = i - CQ_X;  }
    else if (i < CQ_WK) { src = wk; dst = wkh; j = i - CQ_WQ; }
    else if (i < CQ_WV) { src = wv; dst = wvh; j = i - CQ_WK; }
    else                { src = wo; dst = woh; j = i - CQ_WV; }
    float4 v = src[j];
    size_t e = j * 4;
    dst[e]     = __float2half(v.x);
    dst[e + 1] = __float2half(v.y);
    dst[e + 2] = __float2half(v.z);
    dst[e + 3] = __float2half(v.w);
}

// ============================================================================
// shared GEMM config
// ============================================================================
constexpr int HROWB  = 80;                 // bytes per smem row (40 halves)
constexpr int GTILE  = 128 * HROWB;        // 10240 B
constexpr int GSTAGE = 2 * GTILE;
constexpr int GEMM16_SMEM = 4 * GSTAGE;    // 81920

// mainloop, SAFE ordering (wait_group -> barrier -> issue -> read):
// both k-sections' fragments loaded back-to-back, then all 32 MMAs.
// All fragment loads/consumption stay inside one iteration (no cross-stage
// register hazards; cp.async visibility guaranteed by wait+barrier).
template <typename EPI>
__device__ __forceinline__
void gemm16_body(const __half* __restrict__ A, const __half* __restrict__ Bw,
                 int m0, int n0loc, EPI epi)
{
    extern __shared__ char sm[];
    const uint32_t sb = smem_u32(sm);
    const int tid = threadIdx.x;
    const int wid = tid >> 5;
    const int lane = tid & 31;
    const int wm = (wid >> 2) * 64;
    const int wn = (wid & 3) * 32;

    const __half* Abase = A  + (size_t)m0 * K2;
    const __half* Bbase = Bw + (size_t)n0loc * DMODEL;

    const int grp = lane >> 3, lr = lane & 7;
    const uint32_t aoff0 = (wm + (grp & 1) * 8 + lr) * HROWB + (grp >> 1) * 16;
    const uint32_t boff0 = GTILE + (wn + (grp >> 1) * 8 + lr) * HROWB
                         + (grp & 1) * 16;

    float acc[4][4][4];
    #pragma unroll
    for (int mf = 0; mf < 4; mf++)
        #pragma unroll
        for (int nf = 0; nf < 4; nf++)
            #pragma unroll
            for (int e = 0; e < 4; e++) acc[mf][nf][e] = 0.f;

    auto issue = [&](int c) {
        if (c >= NCH2) return;
        const uint32_t st = sb + (c & 3) * GSTAGE;
        const __half* Ag = Abase + c * 32;
        const __half* Bg = Bbase + (c & 63) * 32;
        #pragma unroll
        for (int t = 0; t < 2; t++) {
            int i = tid + t * 256;
            int row = i >> 2, seg = i & 3;
            cp16(st + row * HROWB + seg * 16, Ag + (size_t)row * K2 + seg * 8);
        }
        #pragma unroll
        for (int t = 0; t < 2; t++) {
            int i = tid + t * 256;
            int row = i >> 2, seg = i & 3;
            cp16(st + GTILE + row * HROWB + seg * 16,
                 Bg + (size_t)row * DMODEL + seg * 8);
        }
    };

    auto ldfrags = [&](uint32_t base, uint32_t koff,
                       uint32_t (&ar)[4][4], uint32_t (&br)[2][4]) {
        #pragma unroll
        for (int mf = 0; mf < 4; mf++)
            ldsm_x4(ar[mf], base + aoff0 + mf * (16 * HROWB) + koff);
        #pragma unroll
        for (int nf2 = 0; nf2 < 2; nf2++)
            ldsm_x4(br[nf2], base + boff0 + nf2 * (16 * HROWB) + koff);
    };
    auto domma = [&](uint32_t (&ar)[4][4], uint32_t (&br)[2][4]) {
        #pragma unroll
        for (int mf = 0; mf < 4; mf++)
            #pragma unroll
            for (int nf = 0; nf < 4; nf++)
                mma_f16(acc[mf][nf], ar[mf], &br[nf >> 1][(nf & 1) * 2]);
    };

    issue(0); asm volatile("cp.async.commit_group;" ::: "memory");
    issue(1); asm volatile("cp.async.commit_group;" ::: "memory");
    issue(2); asm volatile("cp.async.commit_group;" ::: "memory");

    uint32_t arA[4][4], brA[2][4], arB[4][4], brB[2][4];

    for (int c = 0; c < NCH2; c++) {
        asm volatile("cp.async.wait_group 2;" ::: "memory"); // stage c (own) done
        __syncthreads();        // all warps waited -> stage c fully visible;
                                // all warps finished consuming stage c-1
        issue(c + 3);           // overwrite stage (c-1)&3 (safe per barrier)
        asm volatile("cp.async.commit_group;" ::: "memory");

        const uint32_t st = sb + (c & 3) * GSTAGE;
        ldfrags(st, 0,  arA, brA);   // both sections back-to-back:
        ldfrags(st, 32, arB, brB);   // section-1 latency hides behind mma(A)
        domma(arA, brA);
        domma(arB, brB);
    }

    const int lr4 = lane >> 2, lc2 = (lane & 3) * 2;
    #pragma unroll
    for (int mf = 0; mf < 4; mf++) {
        int r = m0 + wm + mf * 16 + lr4;
        #pragma unroll
        for (int nf = 0; nf < 4; nf++) {
            int cc = wn + nf * 8 + lc2;
            epi(r,     cc, acc[mf][nf][0], acc[mf][nf][1]);
            epi(r + 8, cc, acc[mf][nf][2], acc[mf][nf][3]);
        }
    }
}

// ============================================================================
// fused QKV projection (epilogue: RoPE + fp16 split)
// ============================================================================
__global__ __launch_bounds__(256, 2)
void qkv_gemm(const __half* __restrict__ x2,
              const __half* __restrict__ wqh, const __half* __restrict__ wkh,
              const __half* __restrict__ wvh,
              const float* __restrict__ fc, const float* __restrict__ fs,
              __half* __restrict__ qh2, __half* __restrict__ ql2,
              __half* __restrict__ kh2, __half* __restrict__ vh2)
{
    const int bx = blockIdx.x;
    const int m0 = blockIdx.y * 128;

    if (bx < 16) {
        const int n0 = bx * 128;
        gemm16_body(x2, wqh, m0, n0,
            [&](int r, int cc, float e, float o) {
                int col = n0 + cc;
                int s = r & (SEQ - 1);
                int p = (col & 127) >> 1;
                float c  = fc[s * 64 + p];
                float si = fs[s * 64 + p];
                float re = e * c - o * si;
                float ro = e * si + o * c;
                uint32_t hi, lo;
                split2h(re, ro, hi, lo);
                size_t idx = (size_t)r * QE + col;
                *(uint32_t*)(qh2 + idx) = hi;
                *(uint32_t*)(ql2 + idx) = lo;
            });
    } else if (bx < 20) {
        const int n0 = (bx - 16) * 128;
        gemm16_body(x2, wkh, m0, n0,
            [&](int r, int cc, float e, float o) {
                int col = n0 + cc;
                int s = r & (SEQ - 1);
                int p = (col & 127) >> 1;
                float c  = fc[s * 64 + p];
                float si = fs[s * 64 + p];
                float re = e * c - o * si;
                float ro = e * si + o * c;
                *(uint32_t*)(kh2 + (size_t)r * KVE + col) = pack_f16(re, ro);
            });
    } else {
        const int n0 = (bx - 20) * 128;
        gemm16_body(x2, wvh, m0, n0,
            [&](int r, int cc, float e, float o) {
                *(uint32_t*)(vh2 + (size_t)r * KVE + n0 + cc) = pack_f16(e, o);
            });
    }
}

// ============================================================================
// output projection
// ============================================================================
__global__ __launch_bounds__(256, 2)
void wo_gemm(const __half* __restrict__ ao2, const __half* __restrict__ woh,
             float* __restrict__ out)
{
    const int n0 = blockIdx.x * 128;
    const int m0 = blockIdx.y * 128;
    gemm16_body(ao2, woh, m0, n0,
        [&](int r, int cc, float e, float o) {
            *(float2*)(out + (size_t)r * DMODEL + n0 + cc) = make_float2(e, o);
        });
}

// ============================================================================
// fp16 2-term tensor-core causal flash attention (Br=128, Bc=64)
// Q fragments in registers; 4-stage KV pipeline (wait->barrier->issue order);
// intra-stage double-buffered inner ldsm (consumed before next barrier).
// ============================================================================
constexpr int ATT_STRIDE = 136;
constexpr int ROWB  = ATT_STRIDE * 2;        // 272 B
constexpr int QTILE = 128 * ROWB;            // 34816
constexpr int KTILE = 64 * ROWB;             // 17408
constexpr int KVSTAGE = 2 * KTILE;           // 34816
constexpr int ATT_SMEM = 4 * KVSTAGE;        // 139264

__global__ __launch_bounds__(256)
void attn_mma(const __half* __restrict__ Qh, const __half* __restrict__ Ql,
              const __half* __restrict__ Kh, const __half* __restrict__ Vh,
              __half* __restrict__ ao2)
{
    extern __shared__ char sm[];
    const uint32_t sb = smem_u32(sm);

    const int qb = gridDim.x - 1 - blockIdx.x;
    const int h  = blockIdx.y;
    const int b  = blockIdx.z;
    const int kh = h >> 2;
    const int tid = threadIdx.x;
    const int wid = tid >> 5;
    const int lane = tid & 31;
    const int q0 = qb * 128;
    const int nkb = q0 / 64 + 2;

    const int grp = lane >> 3, lr = lane & 7;

    // ---- load Q (hi+lo) into smem stages 0-1, hoist fragments to registers
    {
        const size_t qrow = ((size_t)(b * SEQ + q0) * NH + h) * HD;
        for (int i = tid; i < 2048; i += 256) {
            int r = i >> 4, ch = i & 15;
            size_t g = qrow + (size_t)r * NH * HD + ch * 8;
            uint32_t so = r * ROWB + ch * 16;
            cp16(sb + so, Qh + g);
            cp16(sb + QTILE + so, Ql + g);
        }
    }
    asm volatile("cp.async.commit_group;" ::: "memory");
    asm volatile("cp.async.wait_group 0;" ::: "memory");
    __syncthreads();

    uint32_t qh_r[8][4], ql_r[8][4];
    {
        const uint32_t qa_h = sb + (wid * 16 + (grp & 1) * 8 + lr) * ROWB
                            + (grp >> 1) * 16;
        const uint32_t qa_l = qa_h + QTILE;
        #pragma unroll
        for (int ks = 0; ks < 8; ks++) {
            ldsm_x4(qh_r[ks], qa_h + ks * 32);
            ldsm_x4(ql_r[ks], qa_l + ks * 32);
        }
    }
    // force Q-frag consumption visibility before smem reuse: a dummy use is
    // unnecessary — frags are consumed in the loop, but reads must complete
    // before KV cp.async overwrites stages 0-1. Barrier + first-use ordering
    // proved fine in R8 (same pattern, passing).
    __syncthreads();

    auto issue_kv = [&](int kb) {
        const uint32_t st = sb + (kb & 3) * KVSTAGE;
        const size_t kvrow = ((size_t)(b * SEQ + kb * 64) * NKV + kh) * HD;
        for (int i = tid; i < 1024; i += 256) {
            int r = i >> 4, ch = i & 15;
            size_t g = kvrow + (size_t)r * NKV * HD + ch * 8;
            uint32_t so = r * ROWB + ch * 16;
            cp16(st + so,         Kh + g);
            cp16(st + KTILE + so, Vh + g);
        }
    };

    #pragma unroll
    for (int p = 0; p < 3; p++) {
        if (p < nkb) issue_kv(p);
        asm volatile("cp.async.commit_group;" ::: "memory");
    }

    const uint32_t kboff = ((grp >> 1) * 8 + lr) * ROWB + (grp & 1) * 16;
    const uint32_t vboff = ((grp & 1) * 8 + lr) * ROWB + (grp >> 1) * 16;

    float m_[2] = {-1e30f, -1e30f};
    float l_[2] = {0.f, 0.f};
    float of[16][4];
    #pragma unroll
    for (int nf = 0; nf < 16; nf++)
        #pragma unroll
        for (int e = 0; e < 4; e++) of[nf][e] = 0.f;

    const float scale = 0.08838834764831845f;
    const int rbase = q0 + wid * 16 + (lane >> 2);

    for (int kb = 0; kb < nkb; kb++) {
        asm volatile("cp.async.wait_group 2;" ::: "memory");
        __syncthreads();
        if (kb + 3 < nkb) issue_kv(kb + 3);
        asm volatile("cp.async.commit_group;" ::: "memory");

        const uint32_t st = sb + (kb & 3) * KVSTAGE;

        // ---- S = Q K^T, double-buffered K frags (intra-stage) ----
        float sf[8][4];
        #pragma unroll
        for (int f = 0; f < 8; f++)
            #pragma unroll
            for (int e = 0; e < 4; e++) sf[f][e] = 0.f;

        {
            uint32_t bh0[4], bh1[4];
            ldsm_x4(bh0, st + kboff);
            #pragma unroll
            for (int t = 0; t < 32; t++) {
                const int ks = t >> 2, nb = t & 3;
                uint32_t* cur = (t & 1) ? bh1 : bh0;
                uint32_t* nxt = (t & 1) ? bh0 : bh1;
                if (t + 1 < 32) {
                    const int ks2 = (t + 1) >> 2, nb2 = (t + 1) & 3;
                    ldsm_x4(nxt, st + kboff + nb2 * 16 * ROWB + ks2 * 32);
                }
                mma_f16(sf[2 * nb],     qh_r[ks], cur);
                mma_f16(sf[2 * nb + 1], qh_r[ks], cur + 2);
                mma_f16(sf[2 * nb],     ql_r[ks], cur);
                mma_f16(sf[2 * nb + 1], ql_r[ks], cur + 2);
            }
        }

        // ---- scale + mask + online softmax ----
        float mx[2] = {-1e30f, -1e30f};
        #pragma unroll
        for (int f = 0; f < 8; f++)
            #pragma unroll
            for (int e = 0; e < 4; e++) {
                float v = sf[f][e] * scale;
                int col = kb * 64 + f * 8 + ((lane & 3) << 1) + (e & 1);
                int row = rbase + ((e & 2) << 2);
                v = (col > row) ? -1e30f : v;
                sf[f][e] = v;
                mx[e >> 1] = fmaxf(mx[e >> 1], v);
            }
        #pragma unroll
        for (int e = 0; e < 2; e++) {
            mx[e] = fmaxf(mx[e], __shfl_xor_sync(0xffffffffu, mx[e], 1));
            mx[e] = fmaxf(mx[e], __shfl_xor_sync(0xffffffffu, mx[e], 2));
        }
        float mn[2], alp[2], rs[2] = {0.f, 0.f};
        #pragma unroll
        for (int e = 0; e < 2; e++) {
            mn[e]  = fmaxf(m_[e], mx[e]);
            alp[e] = __expf(m_[e] - mn[e]);
            m_[e]  = mn[e];
        }
        #pragma unroll
        for (int f = 0; f < 8; f++)
            #pragma unroll
            for (int e = 0; e < 4; e++) {
                float p = __expf(sf[f][e] - mn[e >> 1]);
                sf[f][e] = p;
                rs[e >> 1] += p;
            }
        #pragma unroll
        for (int e = 0; e < 2; e++) {
            rs[e] += __shfl_xor_sync(0xffffffffu, rs[e], 1);
            rs[e] += __shfl_xor_sync(0xffffffffu, rs[e], 2);
            l_[e] = l_[e] * alp[e] + rs[e];
        }
        #pragma unroll
        for (int nf = 0; nf < 16; nf++) {
            of[nf][0] *= alp[0]; of[nf][1] *= alp[0];
            of[nf][2] *= alp[1]; of[nf][3] *= alp[1];
        }

        // ---- O += P V, P splits hoisted, double-buffered V frags ----
        {
            uint32_t PH[4][4], PL[4][4];
            #pragma unroll
            for (int ks = 0; ks < 4; ks++) {
                split2h(sf[2 * ks][0],     sf[2 * ks][1],     PH[ks][0], PL[ks][0]);
                split2h(sf[2 * ks][2],     sf[2 * ks][3],     PH[ks][1], PL[ks][1]);
                split2h(sf[2 * ks + 1][0], sf[2 * ks + 1][1], PH[ks][2], PL[ks][2]);
                split2h(sf[2 * ks + 1][2], sf[2 * ks + 1][3], PH[ks][3], PL[ks][3]);
            }
            uint32_t vv0[4], vv1[4];
            ldsm_x4_t(vv0, st + KTILE + vboff);
            #pragma unroll
            for (int t = 0; t < 32; t++) {
                const int ks = t >> 3, nb = t & 7;
                uint32_t* cur = (t & 1) ? vv1 : vv0;
                uint32_t* nxt = (t & 1) ? vv0 : vv1;
                if (t + 1 < 32) {
                    const int ks2 = (t + 1) >> 3, nb2 = (t + 1) & 7;
                    ldsm_x4_t(nxt, st + KTILE + vboff + ks2 * 16 * ROWB + nb2 * 32);
                }
                mma_f16(of[2 * nb],     PH[ks], cur);
                mma_f16(of[2 * nb + 1], PH[ks], cur + 2);
                mma_f16(of[2 * nb],     PL[ks], cur);
                mma_f16(of[2 * nb + 1], PL[ks], cur + 2);
            }
        }
    }

    // ---- epilogue: normalize + hi/lo split into ao2 ----
    float inv0 = 1.f / l_[0], inv1 = 1.f / l_[1];
    size_t b0 = (size_t)(b * SEQ + rbase) * K2 + h * HD + ((lane & 3) << 1);
    size_t b1 = b0 + (size_t)8 * K2;
    #pragma unroll
    for (int nf = 0; nf < 16; nf++) {
        uint32_t hi, lo;
        split2h(of[nf][0] * inv0, of[nf][1] * inv0, hi, lo);
        *(uint32_t*)(ao2 + b0 + nf * 8)          = hi;
        *(uint32_t*)(ao2 + b0 + DMODEL + nf * 8) = lo;
        split2h(of[nf][2] * inv1, of[nf][3] * inv1, hi, lo);
        *(uint32_t*)(ao2 + b1 + nf * 8)          = hi;
        *(uint32_t*)(ao2 + b1 + DMODEL + nf * 8) = lo;
    }
}

// ============================================================================
// host launcher
// ============================================================================
extern "C" void kernel_launch(void* const* d_in, const int* in_sizes, int n_in,
                              void* d_out, int out_size)
{
    const float* x  = (const float*)d_in[0];
    const float* fc = (const float*)d_in[1];
    const float* fs = (const float*)d_in[2];
    const float* wq = (const float*)d_in[4];
    const float* wk = (const float*)d_in[5];
    const float* wv = (const float*)d_in[6];
    const float* wo = (const float*)d_in[7];
    float* out = (float*)d_out;

    __half *x2, *ao2, *wqh, *wkh, *wvh, *woh, *qh2, *ql2, *kh2, *vh2;
    cudaGetSymbolAddress((void**)&x2,  g_x2);
    cudaGetSymbolAddress((void**)&ao2, g_ao2);
    cudaGetSymbolAddress((void**)&wqh, g_wqh);
    cudaGetSymbolAddress((void**)&wkh, g_wkh);
    cudaGetSymbolAddress((void**)&wvh, g_wvh);
    cudaGetSymbolAddress((void**)&woh, g_woh);
    cudaGetSymbolAddress((void**)&qh2, g_qh2);
    cudaGetSymbolAddress((void**)&ql2, g_ql2);
    cudaGetSymbolAddress((void**)&kh2, g_kh2);
    cudaGetSymbolAddress((void**)&vh2, g_vh2);

    cudaFuncSetAttribute(qkv_gemm, cudaFuncAttributeMaxDynamicSharedMemorySize,
                         GEMM16_SMEM);
    cudaFuncSetAttribute(wo_gemm, cudaFuncAttributeMaxDynamicSharedMemorySize,
                         GEMM16_SMEM);
    cudaFuncSetAttribute(attn_mma, cudaFuncAttributeMaxDynamicSharedMemorySize,
                         ATT_SMEM);

    // ---- single merged conversion launch ----
    convert_all<<<(unsigned)(CQ_WO / 256), 256>>>(
        (const float4*)x, (const float4*)wq, (const float4*)wk,
        (const float4*)wv, (const float4*)wo, x2, wqh, wkh, wvh, woh);

    // ---- fused QKV projection + RoPE + fp16 split ----
    qkv_gemm<<<dim3(24, MROWS / 128), 256, GEMM16_SMEM>>>(
        x2, wqh, wkh, wvh, fc, fs, qh2, ql2, kh2, vh2);

    // ---- tensor-core causal attention ----
    attn_mma<<<dim3(SEQ / 128, NH, BB), 256, ATT_SMEM>>>(qh2, ql2, kh2, vh2, ao2);

    // ---- output projection ----
    wo_gemm<<<dim3(DMODEL / 128, MROWS / 128), 256, GEMM16_SMEM>>>(ao2, woh, out);
}

// round 11
// speedup vs baseline: 7.8847x; 1.1514x over previous
#include <cuda_runtime.h>
#include <cuda_fp16.h>
#include <math.h>
#include <cstdint>

// ---------------- problem constants ----------------
constexpr int BB     = 2;
constexpr int SEQ    = 2048;
constexpr int DMODEL = 2048;
constexpr int NH     = 16;
constexpr int NKV    = 4;
constexpr int HD     = 128;
constexpr int MROWS  = BB * SEQ;     // 4096
constexpr int QE     = NH * HD;      // 2048
constexpr int KVE    = NKV * HD;     // 512
constexpr int K2     = 4096;         // 2-term fp16 split K
constexpr int NCH2   = 128;          // chunks of 32

// ---------------- scratch ----------------
__device__ __half g_x2 [(size_t)MROWS * K2];    // [xh | xl]
__device__ __half g_ao2[(size_t)MROWS * K2];    // [aoh | aol]
__device__ __half g_wqh[(size_t)QE     * DMODEL];
__device__ __half g_wkh[(size_t)KVE    * DMODEL];
__device__ __half g_wvh[(size_t)KVE    * DMODEL];
__device__ __half g_woh[(size_t)DMODEL * DMODEL];

__device__ __half g_qh2[(size_t)MROWS * QE];
__device__ __half g_ql2[(size_t)MROWS * QE];
__device__ __half g_kh2[(size_t)MROWS * KVE];
__device__ __half g_vh2[(size_t)MROWS * KVE];

// ---------------- helpers ----------------
__device__ __forceinline__ uint32_t smem_u32(const void* p) {
    uint32_t a;
    asm("{ .reg .u64 t; cvta.to.shared.u64 t, %1; cvt.u32.u64 %0, t; }"
        : "=r"(a) : "l"(p));
    return a;
}
__device__ __forceinline__ void cp16(uint32_t dst, const void* src) {
    asm volatile("cp.async.cg.shared.global [%0], [%1], 16;"
                 :: "r"(dst), "l"(src));
}
__device__ __forceinline__ void ldsm_x4(uint32_t* r, uint32_t addr) {
    asm volatile("ldmatrix.sync.aligned.m8n8.x4.shared.b16 {%0,%1,%2,%3}, [%4];"
                 : "=r"(r[0]), "=r"(r[1]), "=r"(r[2]), "=r"(r[3]) : "r"(addr));
}
__device__ __forceinline__ void ldsm_x4_t(uint32_t* r, uint32_t addr) {
    asm volatile("ldmatrix.sync.aligned.m8n8.x4.trans.shared.b16 {%0,%1,%2,%3}, [%4];"
                 : "=r"(r[0]), "=r"(r[1]), "=r"(r[2]), "=r"(r[3]) : "r"(addr));
}
__device__ __forceinline__ void mma_f16(float* d, const uint32_t* a,
                                        const uint32_t* b) {
    asm volatile(
        "mma.sync.aligned.m16n8k16.row.col.f32.f16.f16.f32 "
        "{%0,%1,%2,%3}, {%4,%5,%6,%7}, {%8,%9}, {%0,%1,%2,%3};"
        : "+f"(d[0]), "+f"(d[1]), "+f"(d[2]), "+f"(d[3])
        : "r"(a[0]), "r"(a[1]), "r"(a[2]), "r"(a[3]), "r"(b[0]), "r"(b[1]));
}
__device__ __forceinline__ uint32_t pack_f16(float lo, float hi) {
    uint32_t r;
    asm("cvt.rn.f16x2.f32 %0, %1, %2;" : "=r"(r) : "f"(hi), "f"(lo));
    return r;
}
__device__ __forceinline__ void split2h(float x, float y, uint32_t& hi, uint32_t& lo) {
    uint32_t h = pack_f16(x, y);
    __half2 hb = *reinterpret_cast<__half2*>(&h);
    lo = pack_f16(x - __half2float(hb.x), y - __half2float(hb.y));
    hi = h;
}

// ============================================================================
// merged conversion kernel
// ============================================================================
constexpr size_t CQ_X  = 2097152;
constexpr size_t CQ_WQ = CQ_X  + 1048576;
constexpr size_t CQ_WK = CQ_WQ + 262144;
constexpr size_t CQ_WV = CQ_WK + 262144;
constexpr size_t CQ_WO = CQ_WV + 1048576;

__global__ __launch_bounds__(256)
void convert_all(const float4* __restrict__ x,  const float4* __restrict__ wq,
                 const float4* __restrict__ wk, const float4* __restrict__ wv,
                 const float4* __restrict__ wo,
                 __half* __restrict__ x2,  __half* __restrict__ wqh,
                 __half* __restrict__ wkh, __half* __restrict__ wvh,
                 __half* __restrict__ woh)
{
    size_t i = (size_t)blockIdx.x * 256 + threadIdx.x;
    if (i < CQ_X) {
        float4 v = x[i];
        size_t e = i * 4;
        size_t r = e >> 11;
        int    c = (int)(e & 2047);
        float xs[4] = {v.x, v.y, v.z, v.w};
        __half* d = x2 + r * (size_t)K2 + c;
        #pragma unroll
        for (int j = 0; j < 4; j++) {
            __half h = __float2half(xs[j]);
            d[j]          = h;
            d[DMODEL + j] = __float2half(xs[j] - __half2float(h));
        }
        return;
    }
    const float4* src; __half* dst; size_t j;
    if      (i < CQ_WQ) { src = wq; dst = wqh; j = i - CQ_X;  }
    else if (i < CQ_WK) { src = wk; dst = wkh; j = i - CQ_WQ; }
    else if (i < CQ_WV) { src = wv; dst = wvh; j = i - CQ_WK; }
    else                { src = wo; dst = woh; j = i - CQ_WV; }
    float4 v = src[j];
    size_t e = j * 4;
    dst[e]     = __float2half(v.x);
    dst[e + 1] = __float2half(v.y);
    dst[e + 2] = __float2half(v.z);
    dst[e + 3] = __float2half(v.w);
}

// ============================================================================
// shared GEMM config — 4 warps, 64x64 warp tiles (fragment-reuse optimized)
// ============================================================================
constexpr int HROWB  = 80;                 // bytes per smem row (40 halves)
constexpr int GTILE  = 128 * HROWB;        // 10240 B
constexpr int GSTAGE = 2 * GTILE;
constexpr int GEMM16_SMEM = 4 * GSTAGE;    // 81920

// 128x128 CTA tile, 128 threads (4 warps in 2x2), BK=32, 4-stage cp.async.
// Per k-section each warp does 8 ldsm.x4 -> 32 MMAs (128 B/MMA vs 192 before),
// dropping below the 128 B/cyc smem-port ceiling -> tensor-bound.
template <typename EPI>
__device__ __forceinline__
void gemm16_body(const __half* __restrict__ A, const __half* __restrict__ Bw,
                 int m0, int n0loc, EPI epi)
{
    extern __shared__ char sm[];
    const uint32_t sb = smem_u32(sm);
    const int tid = threadIdx.x;
    const int wid = tid >> 5;
    const int lane = tid & 31;
    const int wm = (wid >> 1) * 64;    // warp m offset (0/64)
    const int wn = (wid & 1) * 64;     // warp n offset (0/64)

    const __half* Abase = A  + (size_t)m0 * K2;
    const __half* Bbase = Bw + (size_t)n0loc * DMODEL;

    const int grp = lane >> 3, lr = lane & 7;
    const uint32_t aoff0 = (wm + (grp & 1) * 8 + lr) * HROWB + (grp >> 1) * 16;
    const uint32_t boff0 = GTILE + (wn + (grp >> 1) * 8 + lr) * HROWB
                         + (grp & 1) * 16;

    float acc[4][8][4];
    #pragma unroll
    for (int mf = 0; mf < 4; mf++)
        #pragma unroll
        for (int nf = 0; nf < 8; nf++)
            #pragma unroll
            for (int e = 0; e < 4; e++) acc[mf][nf][e] = 0.f;

    auto issue = [&](int c) {
        if (c >= NCH2) return;
        const uint32_t st = sb + (c & 3) * GSTAGE;
        const __half* Ag = Abase + c * 32;
        const __half* Bg = Bbase + (c & 63) * 32;
        #pragma unroll
        for (int t = 0; t < 4; t++) {
            int i = tid + t * 128;
            int row = i >> 2, seg = i & 3;
            cp16(st + row * HROWB + seg * 16, Ag + (size_t)row * K2 + seg * 8);
        }
        #pragma unroll
        for (int t = 0; t < 4; t++) {
            int i = tid + t * 128;
            int row = i >> 2, seg = i & 3;
            cp16(st + GTILE + row * HROWB + seg * 16,
                 Bg + (size_t)row * DMODEL + seg * 8);
        }
    };

    auto ldfrags = [&](uint32_t base, uint32_t koff,
                       uint32_t (&ar)[4][4], uint32_t (&br)[4][4]) {
        #pragma unroll
        for (int mf = 0; mf < 4; mf++)
            ldsm_x4(ar[mf], base + aoff0 + mf * (16 * HROWB) + koff);
        #pragma unroll
        for (int nf2 = 0; nf2 < 4; nf2++)
            ldsm_x4(br[nf2], base + boff0 + nf2 * (16 * HROWB) + koff);
    };
    auto domma = [&](uint32_t (&ar)[4][4], uint32_t (&br)[4][4]) {
        #pragma unroll
        for (int mf = 0; mf < 4; mf++)
            #pragma unroll
            for (int nf = 0; nf < 8; nf++)
                mma_f16(acc[mf][nf], ar[mf], &br[nf >> 1][(nf & 1) * 2]);
    };

    issue(0); asm volatile("cp.async.commit_group;" ::: "memory");
    issue(1); asm volatile("cp.async.commit_group;" ::: "memory");
    issue(2); asm volatile("cp.async.commit_group;" ::: "memory");

    uint32_t ar[4][4], br[4][4];

    for (int c = 0; c < NCH2; c++) {
        asm volatile("cp.async.wait_group 2;" ::: "memory"); // own copies of stage c done
        __syncthreads();        // all warps waited -> stage c fully visible;
                                // all warps finished consuming stage c-1
        issue(c + 3);           // overwrite stage (c-1)&3 (safe per barrier)
        asm volatile("cp.async.commit_group;" ::: "memory");

        const uint32_t st = sb + (c & 3) * GSTAGE;
        ldfrags(st, 0, ar, br);
        domma(ar, br);
        ldfrags(st, 32, ar, br);
        domma(ar, br);
    }

    const int lr4 = lane >> 2, lc2 = (lane & 3) * 2;
    #pragma unroll
    for (int mf = 0; mf < 4; mf++) {
        int r = m0 + wm + mf * 16 + lr4;
        #pragma unroll
        for (int nf = 0; nf < 8; nf++) {
            int cc = wn + nf * 8 + lc2;
            epi(r,     cc, acc[mf][nf][0], acc[mf][nf][1]);
            epi(r + 8, cc, acc[mf][nf][2], acc[mf][nf][3]);
        }
    }
}

// ============================================================================
// fused QKV projection (epilogue: RoPE + fp16 split)
// ============================================================================
__global__ __launch_bounds__(128, 2)
void qkv_gemm(const __half* __restrict__ x2,
              const __half* __restrict__ wqh, const __half* __restrict__ wkh,
              const __half* __restrict__ wvh,
              const float* __restrict__ fc, const float* __restrict__ fs,
              __half* __restrict__ qh2, __half* __restrict__ ql2,
              __half* __restrict__ kh2, __half* __restrict__ vh2)
{
    const int bx = blockIdx.x;
    const int m0 = blockIdx.y * 128;

    if (bx < 16) {
        const int n0 = bx * 128;
        gemm16_body(x2, wqh, m0, n0,
            [&](int r, int cc, float e, float o) {
                int col = n0 + cc;
                int s = r & (SEQ - 1);
                int p = (col & 127) >> 1;
                float c  = fc[s * 64 + p];
                float si = fs[s * 64 + p];
                float re = e * c - o * si;
                float ro = e * si + o * c;
                uint32_t hi, lo;
                split2h(re, ro, hi, lo);
                size_t idx = (size_t)r * QE + col;
                *(uint32_t*)(qh2 + idx) = hi;
                *(uint32_t*)(ql2 + idx) = lo;
            });
    } else if (bx < 20) {
        const int n0 = (bx - 16) * 128;
        gemm16_body(x2, wkh, m0, n0,
            [&](int r, int cc, float e, float o) {
                int col = n0 + cc;
                int s = r & (SEQ - 1);
                int p = (col & 127) >> 1;
                float c  = fc[s * 64 + p];
                float si = fs[s * 64 + p];
                float re = e * c - o * si;
                float ro = e * si + o * c;
                *(uint32_t*)(kh2 + (size_t)r * KVE + col) = pack_f16(re, ro);
            });
    } else {
        const int n0 = (bx - 20) * 128;
        gemm16_body(x2, wvh, m0, n0,
            [&](int r, int cc, float e, float o) {
                *(uint32_t*)(vh2 + (size_t)r * KVE + n0 + cc) = pack_f16(e, o);
            });
    }
}

// ============================================================================
// output projection
// ============================================================================
__global__ __launch_bounds__(128, 2)
void wo_gemm(const __half* __restrict__ ao2, const __half* __restrict__ woh,
             float* __restrict__ out)
{
    const int n0 = blockIdx.x * 128;
    const int m0 = blockIdx.y * 128;
    gemm16_body(ao2, woh, m0, n0,
        [&](int r, int cc, float e, float o) {
            *(float2*)(out + (size_t)r * DMODEL + n0 + cc) = make_float2(e, o);
        });
}

// ============================================================================
// fp16 2-term tensor-core causal flash attention (Br=128, Bc=64)
// (unchanged from R10 passing version)
// ============================================================================
constexpr int ATT_STRIDE = 136;
constexpr int ROWB  = ATT_STRIDE * 2;        // 272 B
constexpr int QTILE = 128 * ROWB;            // 34816
constexpr int KTILE = 64 * ROWB;             // 17408
constexpr int KVSTAGE = 2 * KTILE;           // 34816
constexpr int ATT_SMEM = 4 * KVSTAGE;        // 139264

__global__ __launch_bounds__(256)
void attn_mma(const __half* __restrict__ Qh, const __half* __restrict__ Ql,
              const __half* __restrict__ Kh, const __half* __restrict__ Vh,
              __half* __restrict__ ao2)
{
    extern __shared__ char sm[];
    const uint32_t sb = smem_u32(sm);

    const int qb = gridDim.x - 1 - blockIdx.x;
    const int h  = blockIdx.y;
    const int b  = blockIdx.z;
    const int kh = h >> 2;
    const int tid = threadIdx.x;
    const int wid = tid >> 5;
    const int lane = tid & 31;
    const int q0 = qb * 128;
    const int nkb = q0 / 64 + 2;

    const int grp = lane >> 3, lr = lane & 7;

    {
        const size_t qrow = ((size_t)(b * SEQ + q0) * NH + h) * HD;
        for (int i = tid; i < 2048; i += 256) {
            int r = i >> 4, ch = i & 15;
            size_t g = qrow + (size_t)r * NH * HD + ch * 8;
            uint32_t so = r * ROWB + ch * 16;
            cp16(sb + so, Qh + g);
            cp16(sb + QTILE + so, Ql + g);
        }
    }
    asm volatile("cp.async.commit_group;" ::: "memory");
    asm volatile("cp.async.wait_group 0;" ::: "memory");
    __syncthreads();

    uint32_t qh_r[8][4], ql_r[8][4];
    {
        const uint32_t qa_h = sb + (wid * 16 + (grp & 1) * 8 + lr) * ROWB
                            + (grp >> 1) * 16;
        const uint32_t qa_l = qa_h + QTILE;
        #pragma unroll
        for (int ks = 0; ks < 8; ks++) {
            ldsm_x4(qh_r[ks], qa_h + ks * 32);
            ldsm_x4(ql_r[ks], qa_l + ks * 32);
        }
    }
    __syncthreads();

    auto issue_kv = [&](int kb) {
        const uint32_t st = sb + (kb & 3) * KVSTAGE;
        const size_t kvrow = ((size_t)(b * SEQ + kb * 64) * NKV + kh) * HD;
        for (int i = tid; i < 1024; i += 256) {
            int r = i >> 4, ch = i & 15;
            size_t g = kvrow + (size_t)r * NKV * HD + ch * 8;
            uint32_t so = r * ROWB + ch * 16;
            cp16(st + so,         Kh + g);
            cp16(st + KTILE + so, Vh + g);
        }
    };

    #pragma unroll
    for (int p = 0; p < 3; p++) {
        if (p < nkb) issue_kv(p);
        asm volatile("cp.async.commit_group;" ::: "memory");
    }

    const uint32_t kboff = ((grp >> 1) * 8 + lr) * ROWB + (grp & 1) * 16;
    const uint32_t vboff = ((grp & 1) * 8 + lr) * ROWB + (grp >> 1) * 16;

    float m_[2] = {-1e30f, -1e30f};
    float l_[2] = {0.f, 0.f};
    float of[16][4];
    #pragma unroll
    for (int nf = 0; nf < 16; nf++)
        #pragma unroll
        for (int e = 0; e < 4; e++) of[nf][e] = 0.f;

    const float scale = 0.08838834764831845f;
    const int rbase = q0 + wid * 16 + (lane >> 2);

    for (int kb = 0; kb < nkb; kb++) {
        asm volatile("cp.async.wait_group 2;" ::: "memory");
        __syncthreads();
        if (kb + 3 < nkb) issue_kv(kb + 3);
        asm volatile("cp.async.commit_group;" ::: "memory");

        const uint32_t st = sb + (kb & 3) * KVSTAGE;

        float sf[8][4];
        #pragma unroll
        for (int f = 0; f < 8; f++)
            #pragma unroll
            for (int e = 0; e < 4; e++) sf[f][e] = 0.f;

        {
            uint32_t bh0[4], bh1[4];
            ldsm_x4(bh0, st + kboff);
            #pragma unroll
            for (int t = 0; t < 32; t++) {
                const int ks = t >> 2, nb = t & 3;
                uint32_t* cur = (t & 1) ? bh1 : bh0;
                uint32_t* nxt = (t & 1) ? bh0 : bh1;
                if (t + 1 < 32) {
                    const int ks2 = (t + 1) >> 2, nb2 = (t + 1) & 3;
                    ldsm_x4(nxt, st + kboff + nb2 * 16 * ROWB + ks2 * 32);
                }
                mma_f16(sf[2 * nb],     qh_r[ks], cur);
                mma_f16(sf[2 * nb + 1], qh_r[ks], cur + 2);
                mma_f16(sf[2 * nb],     ql_r[ks], cur);
                mma_f16(sf[2 * nb + 1], ql_r[ks], cur + 2);
            }
        }

        float mx[2] = {-1e30f, -1e30f};
        #pragma unroll
        for (int f = 0; f < 8; f++)
            #pragma unroll
            for (int e = 0; e < 4; e++) {
                float v = sf[f][e] * scale;
                int col = kb * 64 + f * 8 + ((lane & 3) << 1) + (e & 1);
                int row = rbase + ((e & 2) << 2);
                v = (col > row) ? -1e30f : v;
                sf[f][e] = v;
                mx[e >> 1] = fmaxf(mx[e >> 1], v);
            }
        #pragma unroll
        for (int e = 0; e < 2; e++) {
            mx[e] = fmaxf(mx[e], __shfl_xor_sync(0xffffffffu, mx[e], 1));
            mx[e] = fmaxf(mx[e], __shfl_xor_sync(0xffffffffu, mx[e], 2));
        }
        float mn[2], alp[2], rs[2] = {0.f, 0.f};
        #pragma unroll
        for (int e = 0; e < 2; e++) {
            mn[e]  = fmaxf(m_[e], mx[e]);
            alp[e] = __expf(m_[e] - mn[e]);
            m_[e]  = mn[e];
        }
        #pragma unroll
        for (int f = 0; f < 8; f++)
            #pragma unroll
            for (int e = 0; e < 4; e++) {
                float p = __expf(sf[f][e] - mn[e >> 1]);
                sf[f][e] = p;
                rs[e >> 1] += p;
            }
        #pragma unroll
        for (int e = 0; e < 2; e++) {
            rs[e] += __shfl_xor_sync(0xffffffffu, rs[e], 1);
            rs[e] += __shfl_xor_sync(0xffffffffu, rs[e], 2);
            l_[e] = l_[e] * alp[e] + rs[e];
        }
        #pragma unroll
        for (int nf = 0; nf < 16; nf++) {
            of[nf][0] *= alp[0]; of[nf][1] *= alp[0];
            of[nf][2] *= alp[1]; of[nf][3] *= alp[1];
        }

        {
            uint32_t PH[4][4], PL[4][4];
            #pragma unroll
            for (int ks = 0; ks < 4; ks++) {
                split2h(sf[2 * ks][0],     sf[2 * ks][1],     PH[ks][0], PL[ks][0]);
                split2h(sf[2 * ks][2],     sf[2 * ks][3],     PH[ks][1], PL[ks][1]);
                split2h(sf[2 * ks + 1][0], sf[2 * ks + 1][1], PH[ks][2], PL[ks][2]);
                split2h(sf[2 * ks + 1][2], sf[2 * ks + 1][3], PH[ks][3], PL[ks][3]);
            }
            uint32_t vv0[4], vv1[4];
            ldsm_x4_t(vv0, st + KTILE + vboff);
            #pragma unroll
            for (int t = 0; t < 32; t++) {
                const int ks = t >> 3, nb = t & 7;
                uint32_t* cur = (t & 1) ? vv1 : vv0;
                uint32_t* nxt = (t & 1) ? vv0 : vv1;
                if (t + 1 < 32) {
                    const int ks2 = (t + 1) >> 3, nb2 = (t + 1) & 7;
                    ldsm_x4_t(nxt, st + KTILE + vboff + ks2 * 16 * ROWB + nb2 * 32);
                }
                mma_f16(of[2 * nb],     PH[ks], cur);
                mma_f16(of[2 * nb + 1], PH[ks], cur + 2);
                mma_f16(of[2 * nb],     PL[ks], cur);
                mma_f16(of[2 * nb + 1], PL[ks], cur + 2);
            }
        }
    }

    float inv0 = 1.f / l_[0], inv1 = 1.f / l_[1];
    size_t b0 = (size_t)(b * SEQ + rbase) * K2 + h * HD + ((lane & 3) << 1);
    size_t b1 = b0 + (size_t)8 * K2;
    #pragma unroll
    for (int nf = 0; nf < 16; nf++) {
        uint32_t hi, lo;
        split2h(of[nf][0] * inv0, of[nf][1] * inv0, hi, lo);
        *(uint32_t*)(ao2 + b0 + nf * 8)          = hi;
        *(uint32_t*)(ao2 + b0 + DMODEL + nf * 8) = lo;
        split2h(of[nf][2] * inv1, of[nf][3] * inv1, hi, lo);
        *(uint32_t*)(ao2 + b1 + nf * 8)          = hi;
        *(uint32_t*)(ao2 + b1 + DMODEL + nf * 8) = lo;
    }
}

// ============================================================================
// host launcher
// ============================================================================
extern "C" void kernel_launch(void* const* d_in, const int* in_sizes, int n_in,
                              void* d_out, int out_size)
{
    const float* x  = (const float*)d_in[0];
    const float* fc = (const float*)d_in[1];
    const float* fs = (const float*)d_in[2];
    const float* wq = (const float*)d_in[4];
    const float* wk = (const float*)d_in[5];
    const float* wv = (const float*)d_in[6];
    const float* wo = (const float*)d_in[7];
    float* out = (float*)d_out;

    __half *x2, *ao2, *wqh, *wkh, *wvh, *woh, *qh2, *ql2, *kh2, *vh2;
    cudaGetSymbolAddress((void**)&x2,  g_x2);
    cudaGetSymbolAddress((void**)&ao2, g_ao2);
    cudaGetSymbolAddress((void**)&wqh, g_wqh);
    cudaGetSymbolAddress((void**)&wkh, g_wkh);
    cudaGetSymbolAddress((void**)&wvh, g_wvh);
    cudaGetSymbolAddress((void**)&woh, g_woh);
    cudaGetSymbolAddress((void**)&qh2, g_qh2);
    cudaGetSymbolAddress((void**)&ql2, g_ql2);
    cudaGetSymbolAddress((void**)&kh2, g_kh2);
    cudaGetSymbolAddress((void**)&vh2, g_vh2);

    cudaFuncSetAttribute(qkv_gemm, cudaFuncAttributeMaxDynamicSharedMemorySize,
                         GEMM16_SMEM);
    cudaFuncSetAttribute(wo_gemm, cudaFuncAttributeMaxDynamicSharedMemorySize,
                         GEMM16_SMEM);
    cudaFuncSetAttribute(attn_mma, cudaFuncAttributeMaxDynamicSharedMemorySize,
                         ATT_SMEM);

    // ---- single merged conversion launch ----
    convert_all<<<(unsigned)(CQ_WO / 256), 256>>>(
        (const float4*)x, (const float4*)wq, (const float4*)wk,
        (const float4*)wv, (const float4*)wo, x2, wqh, wkh, wvh, woh);

    // ---- fused QKV projection + RoPE + fp16 split ----
    qkv_gemm<<<dim3(24, MROWS / 128), 128, GEMM16_SMEM>>>(
        x2, wqh, wkh, wvh, fc, fs, qh2, ql2, kh2, vh2);

    // ---- tensor-core causal attention ----
    attn_mma<<<dim3(SEQ / 128, NH, BB), 256, ATT_SMEM>>>(qh2, ql2, kh2, vh2, ao2);

    // ---- output projection ----
    wo_gemm<<<dim3(DMODEL / 128, MROWS / 128), 128, GEMM16_SMEM>>>(ao2, woh, out);
}